// round 12
// baseline (speedup 1.0000x reference)
#include <cuda_runtime.h>
#include <cuda_fp16.h>

#define PP 4
#define NN 65536
#define DD 128
#define OO 128
#define EE 500000
#define MM 32768
#define TOTAL_ROWS 655360   // 4*N + 12*M
#define NEDGES (16 * EE)    // 8,000,000
#define NTILES 640          // scan tiles of 1024

#define BM 128
#define BK 32
#define AS_STRIDE 36
#define BS_STRIDE 136

#define SCAT_BLKS  2048
#define F2_GRID    6144       // 3 * 2048, pattern [g,g,s]

// ---------------- scratch ----------------
__device__ __half g_FN[(size_t)PP * NN * OO];        // feats @ W_neigh, fp16 (67 MB)
__device__ __half g_SelfM[(size_t)PP * MM * OO];     // (feats@W_self + b) rows [0,M), fp16 (33 MB)
__device__ int   g_cnt[TOTAL_ROWS];
__device__ int   g_off[TOTAL_ROWS];
__device__ int   g_cur[TOTAL_ROWS];
__device__ unsigned long long g_state[NTILES];       // decoupled-lookback tile state
__device__ unsigned short g_sorted_src[NEDGES];      // src ids (<65536) sorted by dst row (16 MB)

__constant__ int c_blkoff[17] = {
    0,      65536,  98304,  131072,
    163840, 196608, 262144, 294912,
    327680, 360448, 393216, 458752,
    491520, 524288, 557056, 589824, 655360};

__device__ __forceinline__ unsigned f2tf32(float v) {
    unsigned r;
    asm("cvt.rna.tf32.f32 %0, %1;" : "=r"(r) : "f"(v));
    return r;
}

// ---------------- GEMM tile worker (non-pipelined tf32 MMA) ----------------
__device__ __forceinline__ void gemm_tile(
    int tileId,
    const float* __restrict__ feats, const float* __restrict__ Ws,
    const float* __restrict__ Wn, const float* __restrict__ bias,
    float* __restrict__ out,
    unsigned (*As)[AS_STRIDE], unsigned (*Bs)[BS_STRIDE])
{
    const int x  = tileId & 511;
    const int yz = tileId >> 9;
    const bool isSelf = (yz & 1) == 0;
    const int s  = yz >> 1;
    const int row0 = x * BM;

    const float* A = feats + (size_t)s * NN * DD;
    const float* B = (isSelf ? Ws : Wn) + (size_t)s * DD * OO;

    const int t    = threadIdx.x;
    const int lane = t & 31;
    const int wid  = t >> 5;
    const int wm   = wid >> 1;
    const int wn   = wid & 1;

    float C[2][8][4];
#pragma unroll
    for (int mf = 0; mf < 2; mf++)
#pragma unroll
        for (int j = 0; j < 8; j++)
#pragma unroll
            for (int q = 0; q < 4; q++) C[mf][j][q] = 0.0f;

    for (int kt = 0; kt < DD; kt += BK) {
#pragma unroll
        for (int q = 0; q < 4; q++) {
            int i  = t + 256 * q;
            int r  = i >> 3;
            int k0 = (i & 7) * 4;
            float4 v = *(const float4*)(A + (size_t)(row0 + r) * DD + kt + k0);
            *(uint4*)&As[r][k0] = make_uint4(f2tf32(v.x), f2tf32(v.y),
                                             f2tf32(v.z), f2tf32(v.w));
        }
#pragma unroll
        for (int q = 0; q < 4; q++) {
            int i  = t + 256 * q;
            int k  = i >> 5;
            int n0 = (i & 31) * 4;
            float4 v = *(const float4*)(B + (size_t)(kt + k) * OO + n0);
            *(uint4*)&Bs[k][n0] = make_uint4(f2tf32(v.x), f2tf32(v.y),
                                             f2tf32(v.z), f2tf32(v.w));
        }
        __syncthreads();

#pragma unroll
        for (int kk = 0; kk < BK; kk += 8) {
            unsigned a[2][4];
#pragma unroll
            for (int mf = 0; mf < 2; mf++) {
                int r = wm * 32 + mf * 16 + (lane >> 2);
                int kc = kk + (lane & 3);
                a[mf][0] = As[r][kc];
                a[mf][1] = As[r + 8][kc];
                a[mf][2] = As[r][kc + 4];
                a[mf][3] = As[r + 8][kc + 4];
            }
#pragma unroll
            for (int j = 0; j < 8; j++) {
                int n = wn * 64 + j * 8 + (lane >> 2);
                unsigned b0 = Bs[kk + (lane & 3)][n];
                unsigned b1 = Bs[kk + (lane & 3) + 4][n];
#pragma unroll
                for (int mf = 0; mf < 2; mf++) {
                    asm("mma.sync.aligned.m16n8k8.row.col.f32.tf32.tf32.f32 "
                        "{%0,%1,%2,%3}, {%4,%5,%6,%7}, {%8,%9}, {%0,%1,%2,%3};"
                        : "+f"(C[mf][j][0]), "+f"(C[mf][j][1]),
                          "+f"(C[mf][j][2]), "+f"(C[mf][j][3])
                        : "r"(a[mf][0]), "r"(a[mf][1]),
                          "r"(a[mf][2]), "r"(a[mf][3]),
                          "r"(b0), "r"(b1));
                }
            }
        }
        __syncthreads();
    }

    const int col0 = wn * 64;
    if (isSelf) {
#pragma unroll
        for (int mf = 0; mf < 2; mf++) {
            int r0 = row0 + wm * 32 + mf * 16 + (lane >> 2);
#pragma unroll
            for (int j = 0; j < 8; j++) {
                int c = col0 + j * 8 + (lane & 3) * 2;
                float b0v = __ldg(bias + s * OO + c);
                float b1v = __ldg(bias + s * OO + c + 1);
                float2 v0 = make_float2(C[mf][j][0] + b0v, C[mf][j][1] + b1v);
                float2 v1 = make_float2(C[mf][j][2] + b0v, C[mf][j][3] + b1v);
                *(float2*)(out + ((size_t)s * NN + r0) * OO + c)     = v0;
                *(float2*)(out + ((size_t)s * NN + r0 + 8) * OO + c) = v1;
                if (r0 < MM) {
                    *(__half2*)(g_SelfM + ((size_t)s * MM + r0) * OO + c)
                        = __floats2half2_rn(v0.x, v0.y);
                    *(__half2*)(g_SelfM + ((size_t)s * MM + r0 + 8) * OO + c)
                        = __floats2half2_rn(v1.x, v1.y);
                }
            }
        }
    } else {
#pragma unroll
        for (int mf = 0; mf < 2; mf++) {
            int r0 = row0 + wm * 32 + mf * 16 + (lane >> 2);
#pragma unroll
            for (int j = 0; j < 8; j++) {
                int c = col0 + j * 8 + (lane & 3) * 2;
                *(__half2*)(g_FN + ((size_t)s * NN + r0) * OO + c)
                    = __floats2half2_rn(C[mf][j][0], C[mf][j][1]);
                *(__half2*)(g_FN + ((size_t)s * NN + r0 + 8) * OO + c)
                    = __floats2half2_rn(C[mf][j][2], C[mf][j][3]);
            }
        }
    }
}

// ---------------- scatter worker (grid-stride over edges) ----------------
__device__ __forceinline__ void scatter_work(
    int chunk, const int* __restrict__ e_src, const int* __restrict__ e_dst)
{
    const int stride = SCAT_BLKS * 256;
    for (int e = chunk * 256 + threadIdx.x; e < NEDGES; e += stride) {
        int blk = e / EE;
        int row = c_blkoff[blk] + __ldg(e_dst + e);
        int pos = atomicAdd(&g_cur[row], 1);
        g_sorted_src[pos] = (unsigned short)__ldg(e_src + e);
    }
}

// ---------------- F2: fused GEMM + scatter (dispatch-interleaved 2:1) ----------------
__global__ __launch_bounds__(256, 2) void gemm_scatter(
    const float* __restrict__ feats, const float* __restrict__ Ws,
    const float* __restrict__ Wn, const float* __restrict__ bias,
    float* __restrict__ out,
    const int* __restrict__ e_src, const int* __restrict__ e_dst)
{
    __shared__ unsigned As[BM][AS_STRIDE];
    __shared__ unsigned Bs[BK][BS_STRIDE];

    const int bx = blockIdx.x;
    const int p  = bx % 3;
    const int g3 = bx / 3;
    if (p < 2) {
        gemm_tile(g3 * 2 + p, feats, Ws, Wn, bias, out, As, Bs);
    } else {
        scatter_work(g3, e_src, e_dst);
    }
}

// ---------------- histogram (int4 vectorized) ----------------
__global__ __launch_bounds__(256) void hist_kernel(const int* __restrict__ e_dst)
{
    int i = blockIdx.x * 256 + threadIdx.x;
    if (i >= NEDGES / 4) return;
    int4 d4 = __ldg((const int4*)e_dst + i);
    int bo = c_blkoff[(i * 4) / EE];      // EE % 4 == 0 -> all 4 in same block
    atomicAdd(&g_cnt[bo + d4.x], 1);
    atomicAdd(&g_cnt[bo + d4.y], 1);
    atomicAdd(&g_cnt[bo + d4.z], 1);
    atomicAdd(&g_cnt[bo + d4.w], 1);
}

// ---------------- single-pass decoupled-lookback scan ----------------
__global__ __launch_bounds__(256) void scan_kernel()
{
    __shared__ int sm[256];
    __shared__ int s_prefix;

    const int tile  = blockIdx.x;
    const int tid   = threadIdx.x;
    const int tbase = tile * 1024;

    int4 v = *(const int4*)(g_cnt + tbase + tid * 4);
    int tsum = v.x + v.y + v.z + v.w;

    sm[tid] = tsum;
    __syncthreads();
    for (int ofs = 1; ofs < 256; ofs <<= 1) {
        int t = (tid >= ofs) ? sm[tid - ofs] : 0;
        __syncthreads();
        sm[tid] += t;
        __syncthreads();
    }
    int excl  = sm[tid] - tsum;
    int total = sm[255];

    if (tid == 0) {
        if (tile == 0) {
            atomicExch(&g_state[0], (2ULL << 32) | (unsigned)total);
            s_prefix = 0;
        } else {
            atomicExch(&g_state[tile], (1ULL << 32) | (unsigned)total);
            long long run = 0;
            int t = tile - 1;
            while (true) {
                unsigned long long st;
                do { st = atomicAdd(&g_state[t], 0ULL); } while ((st >> 32) == 0);
                run += (unsigned)st;
                if ((st >> 32) == 2) break;
                t--;
            }
            atomicExch(&g_state[tile], (2ULL << 32) | (unsigned)(run + total));
            s_prefix = (int)run;
        }
    }
    __syncthreads();

    int base = s_prefix + excl;
    int4 o;
    o.x = base;
    o.y = o.x + v.x;
    o.z = o.y + v.y;
    o.w = o.z + v.z;
    *(int4*)(g_off + tbase + tid * 4) = o;
    *(int4*)(g_cur + tbase + tid * 4) = o;
}

// ---------------- Phase B+C: half-warp per row, fp16 accum, deg<=16 fast path, MLP=4 ----
__device__ __forceinline__ void hacc4(__half2* h, uint4 raw) {
    h[0] = __hadd2(h[0], *(__half2*)&raw.x);
    h[1] = __hadd2(h[1], *(__half2*)&raw.y);
    h[2] = __hadd2(h[2], *(__half2*)&raw.z);
    h[3] = __hadd2(h[3], *(__half2*)&raw.w);
}

__global__ __launch_bounds__(256) void agg_combine(
    float* __restrict__ out, const int* __restrict__ merge)
{
    const int lane = threadIdx.x & 31;
    const int sub  = lane & 15;                     // uint4 index within 256B row
    const int r = blockIdx.x * 16 + ((threadIdx.x >> 5) << 1) + (lane >> 4);

    int blk = 0;
#pragma unroll
    for (int k = 1; k < 16; k++)
        if (r >= c_blkoff[k]) blk = k;
    const int s = blk >> 2, d = blk & 3;
    const int lrow = r - c_blkoff[blk];
    const bool diag = (s == d);

    const int base = g_off[r];
    const int deg  = g_cnt[r];
    const uint4* FNs = (const uint4*)(g_FN + (size_t)s * NN * OO);   // 16 uint4 per row

    // early epilogue loads (latency hidden under the gather loop)
    int tgt = lrow;
    uint4 smr = make_uint4(0u, 0u, 0u, 0u);
    if (!diag) {
        tgt = __ldg(merge + (size_t)blk * MM + lrow);
        smr = *(const uint4*)(g_SelfM + ((size_t)s * MM + lrow) * OO + sub * 8);
    }

    __half2 hz; *(unsigned*)&hz = 0u;
    __half2 ha[4] = {hz, hz, hz, hz};
    __half2 hb[4] = {hz, hz, hz, hz};
    __half2 hc[4] = {hz, hz, hz, hz};
    __half2 hd[4] = {hz, hz, hz, hz};

#define GATHER_BATCH(MSRC, CNT)                                              \
    {                                                                        \
        int j = 0;                                                           \
        for (; j + 4 <= (CNT); j += 4) {                                     \
            int s0 = __shfl_sync(0xffffffffu, (MSRC), j, 16);                \
            int s1 = __shfl_sync(0xffffffffu, (MSRC), j + 1, 16);            \
            int s2 = __shfl_sync(0xffffffffu, (MSRC), j + 2, 16);            \
            int s3 = __shfl_sync(0xffffffffu, (MSRC), j + 3, 16);            \
            uint4 ra = __ldg(FNs + (size_t)s0 * 16 + sub);                   \
            uint4 rb = __ldg(FNs + (size_t)s1 * 16 + sub);                   \
            uint4 rc = __ldg(FNs + (size_t)s2 * 16 + sub);                   \
            uint4 rd = __ldg(FNs + (size_t)s3 * 16 + sub);                   \
            hacc4(ha, ra); hacc4(hb, rb); hacc4(hc, rc); hacc4(hd, rd);      \
        }                                                                    \
        for (; j < (CNT); j++) {                                             \
            int s0 = __shfl_sync(0xffffffffu, (MSRC), j, 16);                \
            uint4 ra = __ldg(FNs + (size_t)s0 * 16 + sub);                   \
            hacc4(ha, ra);                                                   \
        }                                                                    \
    }

    if (deg <= 16) {
        int msrc = (sub < deg) ? (int)__ldg(g_sorted_src + base + sub) : 0;
        GATHER_BATCH(msrc, deg);
    } else {
        for (int i0 = 0; i0 < deg; i0 += 16) {
            int mi = i0 + sub;
            int msrc = (mi < deg) ? (int)__ldg(g_sorted_src + base + mi) : 0;
            int cnt = min(16, deg - i0);
            GATHER_BATCH(msrc, cnt);
        }
    }
#undef GATHER_BATCH

#pragma unroll
    for (int q = 0; q < 4; q++)
        ha[q] = __hadd2(__hadd2(ha[q], hb[q]), __hadd2(hc[q], hd[q]));

    float2 f0 = __half22float2(ha[0]);
    float2 f1 = __half22float2(ha[1]);
    float2 f2 = __half22float2(ha[2]);
    float2 f3 = __half22float2(ha[3]);

    const float invd = (deg > 0) ? (1.0f / (float)deg) : 0.0f;
    const int c0 = sub * 8;     // 8 output cols per lane

    if (diag) {
        if (deg == 0) return;
        float* op = out + ((size_t)d * NN + lrow) * OO + c0;
        asm volatile("red.global.add.v4.f32 [%0], {%1,%2,%3,%4};"
                     :: "l"(op),
                        "f"(f0.x * invd), "f"(f0.y * invd),
                        "f"(f1.x * invd), "f"(f1.y * invd) : "memory");
        asm volatile("red.global.add.v4.f32 [%0], {%1,%2,%3,%4};"
                     :: "l"(op + 4),
                        "f"(f2.x * invd), "f"(f2.y * invd),
                        "f"(f3.x * invd), "f"(f3.y * invd) : "memory");
    } else {
        float2 s0 = __half22float2(*(__half2*)&smr.x);
        float2 s1 = __half22float2(*(__half2*)&smr.y);
        float2 s2 = __half22float2(*(__half2*)&smr.z);
        float2 s3 = __half22float2(*(__half2*)&smr.w);
        float* op = out + ((size_t)d * NN + tgt) * OO + c0;
        asm volatile("red.global.add.v4.f32 [%0], {%1,%2,%3,%4};"
                     :: "l"(op),
                        "f"(fmaf(f0.x, invd, s0.x)), "f"(fmaf(f0.y, invd, s0.y)),
                        "f"(fmaf(f1.x, invd, s1.x)), "f"(fmaf(f1.y, invd, s1.y)) : "memory");
        asm volatile("red.global.add.v4.f32 [%0], {%1,%2,%3,%4};"
                     :: "l"(op + 4),
                        "f"(fmaf(f2.x, invd, s2.x)), "f"(fmaf(f2.y, invd, s2.y)),
                        "f"(fmaf(f3.x, invd, s3.x)), "f"(fmaf(f3.y, invd, s3.y)) : "memory");
    }
}

// ---------------- launch ----------------
extern "C" void kernel_launch(void* const* d_in, const int* in_sizes, int n_in,
                              void* d_out, int out_size)
{
    const float* feats  = (const float*)d_in[0];   // [P,N,D]
    const float* Wself  = (const float*)d_in[1];   // [P,D,O]
    const float* Wneigh = (const float*)d_in[2];   // [P,D,O]
    const float* bias   = (const float*)d_in[3];   // [P,O]
    const int*   e_src  = (const int*)d_in[4];     // [P,P,E]
    const int*   e_dst  = (const int*)d_in[5];     // [P,P,E]
    const int*   merge  = (const int*)d_in[6];     // [P,P,M]
    float* out = (float*)d_out;                    // [P,N,O]

    void* cntPtr = nullptr; cudaGetSymbolAddress(&cntPtr, g_cnt);
    void* stPtr  = nullptr; cudaGetSymbolAddress(&stPtr,  g_state);
    cudaMemsetAsync(cntPtr, 0, sizeof(int) * (size_t)TOTAL_ROWS, 0);
    cudaMemsetAsync(stPtr,  0, sizeof(unsigned long long) * NTILES, 0);

    hist_kernel<<<(NEDGES / 4 + 255) / 256, 256>>>(e_dst);
    scan_kernel<<<NTILES, 256>>>();

    gemm_scatter<<<F2_GRID, 256>>>(feats, Wself, Wneigh, bias, out, e_src, e_dst);

    agg_combine<<<TOTAL_ROWS / 16, 256>>>(out, merge);
}

// round 13
// speedup vs baseline: 1.0396x; 1.0396x over previous
#include <cuda_runtime.h>
#include <cuda_fp16.h>

#define PP 4
#define NN 65536
#define DD 128
#define OO 128
#define EE 500000
#define MM 32768
#define TOTAL_ROWS 655360   // 4*N + 12*M
#define NEDGES (16 * EE)    // 8,000,000
#define NTILES 640          // scan tiles of 1024

#define BM 128
#define BK 32
#define AS_STRIDE 36
#define BS_STRIDE 136

#define SCAT_BLKS  2048
#define F2_GRID    6144       // 3 * 2048, pattern [g,g,s]

// ---------------- scratch ----------------
__device__ __half g_FN[(size_t)PP * NN * OO];        // feats @ W_neigh, fp16 (67 MB)
__device__ __half g_SelfM[(size_t)PP * MM * OO];     // (feats@W_self + b) rows [0,M), fp16 (33 MB)
__device__ int   g_cnt[TOTAL_ROWS];
__device__ int   g_off[TOTAL_ROWS];
__device__ int   g_cur[TOTAL_ROWS];
__device__ unsigned long long g_state[NTILES];       // decoupled-lookback tile state
__device__ unsigned short g_sorted_src[NEDGES];      // src ids (<65536) sorted by dst row (16 MB)

__constant__ int c_blkoff[17] = {
    0,      65536,  98304,  131072,
    163840, 196608, 262144, 294912,
    327680, 360448, 393216, 458752,
    491520, 524288, 557056, 589824, 655360};

__device__ __forceinline__ unsigned f2tf32(float v) {
    unsigned r;
    asm("cvt.rna.tf32.f32 %0, %1;" : "=r"(r) : "f"(v));
    return r;
}

// ---------------- GEMM tile worker (non-pipelined tf32 MMA) ----------------
__device__ __forceinline__ void gemm_tile(
    int tileId,
    const float* __restrict__ feats, const float* __restrict__ Ws,
    const float* __restrict__ Wn, const float* __restrict__ bias,
    float* __restrict__ out,
    unsigned (*As)[AS_STRIDE], unsigned (*Bs)[BS_STRIDE])
{
    const int x  = tileId & 511;
    const int yz = tileId >> 9;
    const bool isSelf = (yz & 1) == 0;
    const int s  = yz >> 1;
    const int row0 = x * BM;

    const float* A = feats + (size_t)s * NN * DD;
    const float* B = (isSelf ? Ws : Wn) + (size_t)s * DD * OO;

    const int t    = threadIdx.x;
    const int lane = t & 31;
    const int wid  = t >> 5;
    const int wm   = wid >> 1;
    const int wn   = wid & 1;

    float C[2][8][4];
#pragma unroll
    for (int mf = 0; mf < 2; mf++)
#pragma unroll
        for (int j = 0; j < 8; j++)
#pragma unroll
            for (int q = 0; q < 4; q++) C[mf][j][q] = 0.0f;

    for (int kt = 0; kt < DD; kt += BK) {
#pragma unroll
        for (int q = 0; q < 4; q++) {
            int i  = t + 256 * q;
            int r  = i >> 3;
            int k0 = (i & 7) * 4;
            float4 v = *(const float4*)(A + (size_t)(row0 + r) * DD + kt + k0);
            *(uint4*)&As[r][k0] = make_uint4(f2tf32(v.x), f2tf32(v.y),
                                             f2tf32(v.z), f2tf32(v.w));
        }
#pragma unroll
        for (int q = 0; q < 4; q++) {
            int i  = t + 256 * q;
            int k  = i >> 5;
            int n0 = (i & 31) * 4;
            float4 v = *(const float4*)(B + (size_t)(kt + k) * OO + n0);
            *(uint4*)&Bs[k][n0] = make_uint4(f2tf32(v.x), f2tf32(v.y),
                                             f2tf32(v.z), f2tf32(v.w));
        }
        __syncthreads();

#pragma unroll
        for (int kk = 0; kk < BK; kk += 8) {
            unsigned a[2][4];
#pragma unroll
            for (int mf = 0; mf < 2; mf++) {
                int r = wm * 32 + mf * 16 + (lane >> 2);
                int kc = kk + (lane & 3);
                a[mf][0] = As[r][kc];
                a[mf][1] = As[r + 8][kc];
                a[mf][2] = As[r][kc + 4];
                a[mf][3] = As[r + 8][kc + 4];
            }
#pragma unroll
            for (int j = 0; j < 8; j++) {
                int n = wn * 64 + j * 8 + (lane >> 2);
                unsigned b0 = Bs[kk + (lane & 3)][n];
                unsigned b1 = Bs[kk + (lane & 3) + 4][n];
#pragma unroll
                for (int mf = 0; mf < 2; mf++) {
                    asm("mma.sync.aligned.m16n8k8.row.col.f32.tf32.tf32.f32 "
                        "{%0,%1,%2,%3}, {%4,%5,%6,%7}, {%8,%9}, {%0,%1,%2,%3};"
                        : "+f"(C[mf][j][0]), "+f"(C[mf][j][1]),
                          "+f"(C[mf][j][2]), "+f"(C[mf][j][3])
                        : "r"(a[mf][0]), "r"(a[mf][1]),
                          "r"(a[mf][2]), "r"(a[mf][3]),
                          "r"(b0), "r"(b1));
                }
            }
        }
        __syncthreads();
    }

    const int col0 = wn * 64;
    if (isSelf) {
#pragma unroll
        for (int mf = 0; mf < 2; mf++) {
            int r0 = row0 + wm * 32 + mf * 16 + (lane >> 2);
#pragma unroll
            for (int j = 0; j < 8; j++) {
                int c = col0 + j * 8 + (lane & 3) * 2;
                float b0v = __ldg(bias + s * OO + c);
                float b1v = __ldg(bias + s * OO + c + 1);
                float2 v0 = make_float2(C[mf][j][0] + b0v, C[mf][j][1] + b1v);
                float2 v1 = make_float2(C[mf][j][2] + b0v, C[mf][j][3] + b1v);
                *(float2*)(out + ((size_t)s * NN + r0) * OO + c)     = v0;
                *(float2*)(out + ((size_t)s * NN + r0 + 8) * OO + c) = v1;
                if (r0 < MM) {
                    *(__half2*)(g_SelfM + ((size_t)s * MM + r0) * OO + c)
                        = __floats2half2_rn(v0.x, v0.y);
                    *(__half2*)(g_SelfM + ((size_t)s * MM + r0 + 8) * OO + c)
                        = __floats2half2_rn(v1.x, v1.y);
                }
            }
        }
    } else {
#pragma unroll
        for (int mf = 0; mf < 2; mf++) {
            int r0 = row0 + wm * 32 + mf * 16 + (lane >> 2);
#pragma unroll
            for (int j = 0; j < 8; j++) {
                int c = col0 + j * 8 + (lane & 3) * 2;
                *(__half2*)(g_FN + ((size_t)s * NN + r0) * OO + c)
                    = __floats2half2_rn(C[mf][j][0], C[mf][j][1]);
                *(__half2*)(g_FN + ((size_t)s * NN + r0 + 8) * OO + c)
                    = __floats2half2_rn(C[mf][j][2], C[mf][j][3]);
            }
        }
    }
}

// ---------------- scatter worker (grid-stride over edges) ----------------
__device__ __forceinline__ void scatter_work(
    int chunk, const int* __restrict__ e_src, const int* __restrict__ e_dst)
{
    const int stride = SCAT_BLKS * 256;
    for (int e = chunk * 256 + threadIdx.x; e < NEDGES; e += stride) {
        int blk = e / EE;
        int row = c_blkoff[blk] + __ldg(e_dst + e);
        int pos = atomicAdd(&g_cur[row], 1);
        g_sorted_src[pos] = (unsigned short)__ldg(e_src + e);
    }
}

// ---------------- F2: fused GEMM + scatter (dispatch-interleaved 2:1) ----------------
__global__ __launch_bounds__(256, 2) void gemm_scatter(
    const float* __restrict__ feats, const float* __restrict__ Ws,
    const float* __restrict__ Wn, const float* __restrict__ bias,
    float* __restrict__ out,
    const int* __restrict__ e_src, const int* __restrict__ e_dst)
{
    __shared__ unsigned As[BM][AS_STRIDE];
    __shared__ unsigned Bs[BK][BS_STRIDE];

    const int bx = blockIdx.x;
    const int p  = bx % 3;
    const int g3 = bx / 3;
    if (p < 2) {
        gemm_tile(g3 * 2 + p, feats, Ws, Wn, bias, out, As, Bs);
    } else {
        scatter_work(g3, e_src, e_dst);
    }
}

// ---------------- histogram (int4 vectorized) ----------------
__global__ __launch_bounds__(256) void hist_kernel(const int* __restrict__ e_dst)
{
    int i = blockIdx.x * 256 + threadIdx.x;
    if (i >= NEDGES / 4) return;
    int4 d4 = __ldg((const int4*)e_dst + i);
    int bo = c_blkoff[(i * 4) / EE];      // EE % 4 == 0 -> all 4 in same block
    atomicAdd(&g_cnt[bo + d4.x], 1);
    atomicAdd(&g_cnt[bo + d4.y], 1);
    atomicAdd(&g_cnt[bo + d4.z], 1);
    atomicAdd(&g_cnt[bo + d4.w], 1);
}

// ---------------- single-pass decoupled-lookback scan ----------------
__global__ __launch_bounds__(256) void scan_kernel()
{
    __shared__ int sm[256];
    __shared__ int s_prefix;

    const int tile  = blockIdx.x;
    const int tid   = threadIdx.x;
    const int tbase = tile * 1024;

    int4 v = *(const int4*)(g_cnt + tbase + tid * 4);
    int tsum = v.x + v.y + v.z + v.w;

    sm[tid] = tsum;
    __syncthreads();
    for (int ofs = 1; ofs < 256; ofs <<= 1) {
        int t = (tid >= ofs) ? sm[tid - ofs] : 0;
        __syncthreads();
        sm[tid] += t;
        __syncthreads();
    }
    int excl  = sm[tid] - tsum;
    int total = sm[255];

    if (tid == 0) {
        if (tile == 0) {
            atomicExch(&g_state[0], (2ULL << 32) | (unsigned)total);
            s_prefix = 0;
        } else {
            atomicExch(&g_state[tile], (1ULL << 32) | (unsigned)total);
            long long run = 0;
            int t = tile - 1;
            while (true) {
                unsigned long long st;
                do { st = atomicAdd(&g_state[t], 0ULL); } while ((st >> 32) == 0);
                run += (unsigned)st;
                if ((st >> 32) == 2) break;
                t--;
            }
            atomicExch(&g_state[tile], (2ULL << 32) | (unsigned)(run + total));
            s_prefix = (int)run;
        }
    }
    __syncthreads();

    int base = s_prefix + excl;
    int4 o;
    o.x = base;
    o.y = o.x + v.x;
    o.z = o.y + v.y;
    o.w = o.z + v.z;
    *(int4*)(g_off + tbase + tid * 4) = o;
    *(int4*)(g_cur + tbase + tid * 4) = o;
}

// ---------------- Phase B+C: half-warp per row, fp16 accum (R11 loop), deg<=16 fast path ----
__global__ __launch_bounds__(256) void agg_combine(
    float* __restrict__ out, const int* __restrict__ merge)
{
    const int lane = threadIdx.x & 31;
    const int sub  = lane & 15;                     // uint4 index within 256B row
    const int r = blockIdx.x * 16 + ((threadIdx.x >> 5) << 1) + (lane >> 4);

    int blk = 0;
#pragma unroll
    for (int k = 1; k < 16; k++)
        if (r >= c_blkoff[k]) blk = k;
    const int s = blk >> 2, d = blk & 3;
    const int lrow = r - c_blkoff[blk];
    const bool diag = (s == d);

    const int base = g_off[r];
    const int deg  = g_cnt[r];
    const uint4* FNs = (const uint4*)(g_FN + (size_t)s * NN * OO);   // 16 uint4 per row

    // early epilogue loads (latency hidden under the gather loop)
    int tgt = lrow;
    uint4 smr = make_uint4(0u, 0u, 0u, 0u);
    if (!diag) {
        tgt = __ldg(merge + (size_t)blk * MM + lrow);
        smr = *(const uint4*)(g_SelfM + ((size_t)s * MM + lrow) * OO + sub * 8);
    }

    __half2 hz; *(unsigned*)&hz = 0u;
    __half2 ha0 = hz, ha1 = hz, ha2 = hz, ha3 = hz;
    __half2 hb0 = hz, hb1 = hz, hb2 = hz, hb3 = hz;

    // two-accumulator 2-way unrolled gather over one 16-edge id batch
#define GATHER_BATCH(MSRC, CNT)                                              \
    {                                                                        \
        int fullc = (CNT) & ~1;                                              \
        int j = 0;                                                           \
        for (; j < fullc; j += 2) {                                          \
            int s0 = __shfl_sync(0xffffffffu, (MSRC), j, 16);                \
            int s1 = __shfl_sync(0xffffffffu, (MSRC), j + 1, 16);            \
            uint4 ra = __ldg(FNs + (size_t)s0 * 16 + sub);                   \
            uint4 rb = __ldg(FNs + (size_t)s1 * 16 + sub);                   \
            ha0 = __hadd2(ha0, *(__half2*)&ra.x);                            \
            ha1 = __hadd2(ha1, *(__half2*)&ra.y);                            \
            ha2 = __hadd2(ha2, *(__half2*)&ra.z);                            \
            ha3 = __hadd2(ha3, *(__half2*)&ra.w);                            \
            hb0 = __hadd2(hb0, *(__half2*)&rb.x);                            \
            hb1 = __hadd2(hb1, *(__half2*)&rb.y);                            \
            hb2 = __hadd2(hb2, *(__half2*)&rb.z);                            \
            hb3 = __hadd2(hb3, *(__half2*)&rb.w);                            \
        }                                                                    \
        if (j < (CNT)) {                                                     \
            int s0 = __shfl_sync(0xffffffffu, (MSRC), j, 16);                \
            uint4 ra = __ldg(FNs + (size_t)s0 * 16 + sub);                   \
            ha0 = __hadd2(ha0, *(__half2*)&ra.x);                            \
            ha1 = __hadd2(ha1, *(__half2*)&ra.y);                            \
            ha2 = __hadd2(ha2, *(__half2*)&ra.z);                            \
            ha3 = __hadd2(ha3, *(__half2*)&ra.w);                            \
        }                                                                    \
    }

    if (deg <= 16) {
        int msrc = (sub < deg) ? (int)__ldg(g_sorted_src + base + sub) : 0;
        GATHER_BATCH(msrc, deg);
    } else {
        for (int i0 = 0; i0 < deg; i0 += 16) {
            int mi = i0 + sub;
            int msrc = (mi < deg) ? (int)__ldg(g_sorted_src + base + mi) : 0;
            int cnt = min(16, deg - i0);
            GATHER_BATCH(msrc, cnt);
        }
    }
#undef GATHER_BATCH

    ha0 = __hadd2(ha0, hb0);
    ha1 = __hadd2(ha1, hb1);
    ha2 = __hadd2(ha2, hb2);
    ha3 = __hadd2(ha3, hb3);

    float2 f0 = __half22float2(ha0);
    float2 f1 = __half22float2(ha1);
    float2 f2 = __half22float2(ha2);
    float2 f3 = __half22float2(ha3);

    const float invd = (deg > 0) ? (1.0f / (float)deg) : 0.0f;
    const int c0 = sub * 8;     // 8 output cols per lane

    if (diag) {
        if (deg == 0) return;
        float* op = out + ((size_t)d * NN + lrow) * OO + c0;
        asm volatile("red.global.add.v4.f32 [%0], {%1,%2,%3,%4};"
                     :: "l"(op),
                        "f"(f0.x * invd), "f"(f0.y * invd),
                        "f"(f1.x * invd), "f"(f1.y * invd) : "memory");
        asm volatile("red.global.add.v4.f32 [%0], {%1,%2,%3,%4};"
                     :: "l"(op + 4),
                        "f"(f2.x * invd), "f"(f2.y * invd),
                        "f"(f3.x * invd), "f"(f3.y * invd) : "memory");
    } else {
        float2 s0 = __half22float2(*(__half2*)&smr.x);
        float2 s1 = __half22float2(*(__half2*)&smr.y);
        float2 s2 = __half22float2(*(__half2*)&smr.z);
        float2 s3 = __half22float2(*(__half2*)&smr.w);
        float* op = out + ((size_t)d * NN + tgt) * OO + c0;
        asm volatile("red.global.add.v4.f32 [%0], {%1,%2,%3,%4};"
                     :: "l"(op),
                        "f"(fmaf(f0.x, invd, s0.x)), "f"(fmaf(f0.y, invd, s0.y)),
                        "f"(fmaf(f1.x, invd, s1.x)), "f"(fmaf(f1.y, invd, s1.y)) : "memory");
        asm volatile("red.global.add.v4.f32 [%0], {%1,%2,%3,%4};"
                     :: "l"(op + 4),
                        "f"(fmaf(f2.x, invd, s2.x)), "f"(fmaf(f2.y, invd, s2.y)),
                        "f"(fmaf(f3.x, invd, s3.x)), "f"(fmaf(f3.y, invd, s3.y)) : "memory");
    }
}

// ---------------- launch ----------------
extern "C" void kernel_launch(void* const* d_in, const int* in_sizes, int n_in,
                              void* d_out, int out_size)
{
    const float* feats  = (const float*)d_in[0];   // [P,N,D]
    const float* Wself  = (const float*)d_in[1];   // [P,D,O]
    const float* Wneigh = (const float*)d_in[2];   // [P,D,O]
    const float* bias   = (const float*)d_in[3];   // [P,O]
    const int*   e_src  = (const int*)d_in[4];     // [P,P,E]
    const int*   e_dst  = (const int*)d_in[5];     // [P,P,E]
    const int*   merge  = (const int*)d_in[6];     // [P,P,M]
    float* out = (float*)d_out;                    // [P,N,O]

    void* cntPtr = nullptr; cudaGetSymbolAddress(&cntPtr, g_cnt);
    void* stPtr  = nullptr; cudaGetSymbolAddress(&stPtr,  g_state);
    cudaMemsetAsync(cntPtr, 0, sizeof(int) * (size_t)TOTAL_ROWS, 0);
    cudaMemsetAsync(stPtr,  0, sizeof(unsigned long long) * NTILES, 0);

    hist_kernel<<<(NEDGES / 4 + 255) / 256, 256>>>(e_dst);
    scan_kernel<<<NTILES, 256>>>();

    gemm_scatter<<<F2_GRID, 256>>>(feats, Wself, Wneigh, bias, out, e_src, e_dst);

    agg_combine<<<TOTAL_ROWS / 16, 256>>>(out, merge);
}

// round 14
// speedup vs baseline: 1.3870x; 1.3341x over previous
#include <cuda_runtime.h>
#include <cuda_fp16.h>

#define PP 4
#define NN 65536
#define DD 128
#define OO 128
#define EE 500000
#define MM 32768
#define TOTAL_ROWS 655360   // 4*N + 12*M
#define NEDGES (16 * EE)    // 8,000,000
#define NTILES 640          // scan tiles of 1024

#define BM 128
#define BK 32
#define AS_STRIDE 36
#define BS_STRIDE 136

#define SCAT_BLKS  2048
#define F2_GRID    6144       // 3 * 2048, pattern [g,g,s]

// ---------------- scratch ----------------
__device__ __half g_FN[(size_t)PP * NN * OO];        // feats @ W_neigh, fp16 (67 MB)
__device__ __half g_SelfM[(size_t)PP * MM * OO];     // (feats@W_self + b) rows [0,M), fp16 (33 MB)
__device__ int   g_cnt[TOTAL_ROWS];
__device__ int   g_off[TOTAL_ROWS];
__device__ int   g_cur[TOTAL_ROWS];
__device__ unsigned long long g_state[NTILES];       // decoupled-lookback tile state
__device__ unsigned short g_sorted_src[NEDGES];      // src ids (<65536) sorted by dst row (16 MB)

__constant__ int c_blkoff[17] = {
    0,      65536,  98304,  131072,
    163840, 196608, 262144, 294912,
    327680, 360448, 393216, 458752,
    491520, 524288, 557056, 589824, 655360};

__device__ __forceinline__ unsigned f2tf32(float v) {
    unsigned r;
    asm("cvt.rna.tf32.f32 %0, %1;" : "=r"(r) : "f"(v));
    return r;
}

// ---------------- GEMM tile worker (non-pipelined tf32 MMA) ----------------
__device__ __forceinline__ void gemm_tile(
    int tileId,
    const float* __restrict__ feats, const float* __restrict__ Ws,
    const float* __restrict__ Wn, const float* __restrict__ bias,
    float* __restrict__ out,
    unsigned (*As)[AS_STRIDE], unsigned (*Bs)[BS_STRIDE])
{
    const int x  = tileId & 511;
    const int yz = tileId >> 9;
    const bool isSelf = (yz & 1) == 0;
    const int s  = yz >> 1;
    const int row0 = x * BM;

    const float* A = feats + (size_t)s * NN * DD;
    const float* B = (isSelf ? Ws : Wn) + (size_t)s * DD * OO;

    const int t    = threadIdx.x;
    const int lane = t & 31;
    const int wid  = t >> 5;
    const int wm   = wid >> 1;
    const int wn   = wid & 1;

    float C[2][8][4];
#pragma unroll
    for (int mf = 0; mf < 2; mf++)
#pragma unroll
        for (int j = 0; j < 8; j++)
#pragma unroll
            for (int q = 0; q < 4; q++) C[mf][j][q] = 0.0f;

    for (int kt = 0; kt < DD; kt += BK) {
#pragma unroll
        for (int q = 0; q < 4; q++) {
            int i  = t + 256 * q;
            int r  = i >> 3;
            int k0 = (i & 7) * 4;
            float4 v = *(const float4*)(A + (size_t)(row0 + r) * DD + kt + k0);
            *(uint4*)&As[r][k0] = make_uint4(f2tf32(v.x), f2tf32(v.y),
                                             f2tf32(v.z), f2tf32(v.w));
        }
#pragma unroll
        for (int q = 0; q < 4; q++) {
            int i  = t + 256 * q;
            int k  = i >> 5;
            int n0 = (i & 31) * 4;
            float4 v = *(const float4*)(B + (size_t)(kt + k) * OO + n0);
            *(uint4*)&Bs[k][n0] = make_uint4(f2tf32(v.x), f2tf32(v.y),
                                             f2tf32(v.z), f2tf32(v.w));
        }
        __syncthreads();

#pragma unroll
        for (int kk = 0; kk < BK; kk += 8) {
            unsigned a[2][4];
#pragma unroll
            for (int mf = 0; mf < 2; mf++) {
                int r = wm * 32 + mf * 16 + (lane >> 2);
                int kc = kk + (lane & 3);
                a[mf][0] = As[r][kc];
                a[mf][1] = As[r + 8][kc];
                a[mf][2] = As[r][kc + 4];
                a[mf][3] = As[r + 8][kc + 4];
            }
#pragma unroll
            for (int j = 0; j < 8; j++) {
                int n = wn * 64 + j * 8 + (lane >> 2);
                unsigned b0 = Bs[kk + (lane & 3)][n];
                unsigned b1 = Bs[kk + (lane & 3) + 4][n];
#pragma unroll
                for (int mf = 0; mf < 2; mf++) {
                    asm("mma.sync.aligned.m16n8k8.row.col.f32.tf32.tf32.f32 "
                        "{%0,%1,%2,%3}, {%4,%5,%6,%7}, {%8,%9}, {%0,%1,%2,%3};"
                        : "+f"(C[mf][j][0]), "+f"(C[mf][j][1]),
                          "+f"(C[mf][j][2]), "+f"(C[mf][j][3])
                        : "r"(a[mf][0]), "r"(a[mf][1]),
                          "r"(a[mf][2]), "r"(a[mf][3]),
                          "r"(b0), "r"(b1));
                }
            }
        }
        __syncthreads();
    }

    const int col0 = wn * 64;
    if (isSelf) {
#pragma unroll
        for (int mf = 0; mf < 2; mf++) {
            int r0 = row0 + wm * 32 + mf * 16 + (lane >> 2);
#pragma unroll
            for (int j = 0; j < 8; j++) {
                int c = col0 + j * 8 + (lane & 3) * 2;
                float b0v = __ldg(bias + s * OO + c);
                float b1v = __ldg(bias + s * OO + c + 1);
                float2 v0 = make_float2(C[mf][j][0] + b0v, C[mf][j][1] + b1v);
                float2 v1 = make_float2(C[mf][j][2] + b0v, C[mf][j][3] + b1v);
                *(float2*)(out + ((size_t)s * NN + r0) * OO + c)     = v0;
                *(float2*)(out + ((size_t)s * NN + r0 + 8) * OO + c) = v1;
                if (r0 < MM) {
                    *(__half2*)(g_SelfM + ((size_t)s * MM + r0) * OO + c)
                        = __floats2half2_rn(v0.x, v0.y);
                    *(__half2*)(g_SelfM + ((size_t)s * MM + r0 + 8) * OO + c)
                        = __floats2half2_rn(v1.x, v1.y);
                }
            }
        }
    } else {
#pragma unroll
        for (int mf = 0; mf < 2; mf++) {
            int r0 = row0 + wm * 32 + mf * 16 + (lane >> 2);
#pragma unroll
            for (int j = 0; j < 8; j++) {
                int c = col0 + j * 8 + (lane & 3) * 2;
                *(__half2*)(g_FN + ((size_t)s * NN + r0) * OO + c)
                    = __floats2half2_rn(C[mf][j][0], C[mf][j][1]);
                *(__half2*)(g_FN + ((size_t)s * NN + r0 + 8) * OO + c)
                    = __floats2half2_rn(C[mf][j][2], C[mf][j][3]);
            }
        }
    }
}

// ---------------- scatter worker (grid-stride over edges) ----------------
__device__ __forceinline__ void scatter_work(
    int chunk, const int* __restrict__ e_src, const int* __restrict__ e_dst)
{
    const int stride = SCAT_BLKS * 256;
    for (int e = chunk * 256 + threadIdx.x; e < NEDGES; e += stride) {
        int blk = e / EE;
        int row = c_blkoff[blk] + __ldg(e_dst + e);
        int pos = atomicAdd(&g_cur[row], 1);
        g_sorted_src[pos] = (unsigned short)__ldg(e_src + e);
    }
}

// ---------------- F2: fused GEMM + scatter (dispatch-interleaved 2:1) ----------------
__global__ __launch_bounds__(256, 2) void gemm_scatter(
    const float* __restrict__ feats, const float* __restrict__ Ws,
    const float* __restrict__ Wn, const float* __restrict__ bias,
    float* __restrict__ out,
    const int* __restrict__ e_src, const int* __restrict__ e_dst)
{
    __shared__ unsigned As[BM][AS_STRIDE];
    __shared__ unsigned Bs[BK][BS_STRIDE];

    const int bx = blockIdx.x;
    const int p  = bx % 3;
    const int g3 = bx / 3;
    if (p < 2) {
        gemm_tile(g3 * 2 + p, feats, Ws, Wn, bias, out, As, Bs);
    } else {
        scatter_work(g3, e_src, e_dst);
    }
}

// ---------------- histogram (int4 vectorized) ----------------
__global__ __launch_bounds__(256) void hist_kernel(const int* __restrict__ e_dst)
{
    int i = blockIdx.x * 256 + threadIdx.x;
    if (i >= NEDGES / 4) return;
    int4 d4 = __ldg((const int4*)e_dst + i);
    int bo = c_blkoff[(i * 4) / EE];      // EE % 4 == 0 -> all 4 in same block
    atomicAdd(&g_cnt[bo + d4.x], 1);
    atomicAdd(&g_cnt[bo + d4.y], 1);
    atomicAdd(&g_cnt[bo + d4.z], 1);
    atomicAdd(&g_cnt[bo + d4.w], 1);
}

// ---------------- single-pass decoupled-lookback scan ----------------
__global__ __launch_bounds__(256) void scan_kernel()
{
    __shared__ int sm[256];
    __shared__ int s_prefix;

    const int tile  = blockIdx.x;
    const int tid   = threadIdx.x;
    const int tbase = tile * 1024;

    int4 v = *(const int4*)(g_cnt + tbase + tid * 4);
    int tsum = v.x + v.y + v.z + v.w;

    sm[tid] = tsum;
    __syncthreads();
    for (int ofs = 1; ofs < 256; ofs <<= 1) {
        int t = (tid >= ofs) ? sm[tid - ofs] : 0;
        __syncthreads();
        sm[tid] += t;
        __syncthreads();
    }
    int excl  = sm[tid] - tsum;
    int total = sm[255];

    if (tid == 0) {
        if (tile == 0) {
            atomicExch(&g_state[0], (2ULL << 32) | (unsigned)total);
            s_prefix = 0;
        } else {
            atomicExch(&g_state[tile], (1ULL << 32) | (unsigned)total);
            long long run = 0;
            int t = tile - 1;
            while (true) {
                unsigned long long st;
                do { st = atomicAdd(&g_state[t], 0ULL); } while ((st >> 32) == 0);
                run += (unsigned)st;
                if ((st >> 32) == 2) break;
                t--;
            }
            atomicExch(&g_state[tile], (2ULL << 32) | (unsigned)(run + total));
            s_prefix = (int)run;
        }
    }
    __syncthreads();

    int base = s_prefix + excl;
    int4 o;
    o.x = base;
    o.y = o.x + v.x;
    o.z = o.y + v.y;
    o.w = o.z + v.z;
    *(int4*)(g_off + tbase + tid * 4) = o;
    *(int4*)(g_cur + tbase + tid * 4) = o;
}

// ---------------- Phase B+C fused: HALF-WARP per row (R11 verbatim) ----
// 8 warps/CTA, 2 rows per warp (one per 16-lane half) -> 16 rows per CTA
__global__ __launch_bounds__(256) void agg_combine(
    float* __restrict__ out, const int* __restrict__ merge)
{
    const int lane = threadIdx.x & 31;
    const int sub  = lane & 15;                     // uint4 index within 256B row
    const int r = blockIdx.x * 16 + ((threadIdx.x >> 5) << 1) + (lane >> 4);

    int blk = 0;
#pragma unroll
    for (int k = 1; k < 16; k++)
        if (r >= c_blkoff[k]) blk = k;
    const int s = blk >> 2, d = blk & 3;
    const int lrow = r - c_blkoff[blk];

    const int base = g_off[r];
    const int deg  = g_cnt[r];
    const uint4* FNs = (const uint4*)(g_FN + (size_t)s * NN * OO);   // 16 uint4 per row

    __half2 hz; *(unsigned*)&hz = 0u;
    __half2 ha0 = hz, ha1 = hz, ha2 = hz, ha3 = hz;
    __half2 hb0 = hz, hb1 = hz, hb2 = hz, hb3 = hz;

    for (int i0 = 0; i0 < deg; i0 += 16) {
        int mi = i0 + sub;
        int msrc = (mi < deg) ? (int)g_sorted_src[base + mi] : 0;
        int cnt = min(16, deg - i0);
        int fullc = cnt & ~1;
        int j = 0;
        for (; j < fullc; j += 2) {
            int s0 = __shfl_sync(0xffffffffu, msrc, j, 16);
            int s1 = __shfl_sync(0xffffffffu, msrc, j + 1, 16);
            uint4 ra = __ldg(FNs + (size_t)s0 * 16 + sub);
            uint4 rb = __ldg(FNs + (size_t)s1 * 16 + sub);
            ha0 = __hadd2(ha0, *(__half2*)&ra.x);
            ha1 = __hadd2(ha1, *(__half2*)&ra.y);
            ha2 = __hadd2(ha2, *(__half2*)&ra.z);
            ha3 = __hadd2(ha3, *(__half2*)&ra.w);
            hb0 = __hadd2(hb0, *(__half2*)&rb.x);
            hb1 = __hadd2(hb1, *(__half2*)&rb.y);
            hb2 = __hadd2(hb2, *(__half2*)&rb.z);
            hb3 = __hadd2(hb3, *(__half2*)&rb.w);
        }
        if (j < cnt) {
            int s0 = __shfl_sync(0xffffffffu, msrc, j, 16);
            uint4 ra = __ldg(FNs + (size_t)s0 * 16 + sub);
            ha0 = __hadd2(ha0, *(__half2*)&ra.x);
            ha1 = __hadd2(ha1, *(__half2*)&ra.y);
            ha2 = __hadd2(ha2, *(__half2*)&ra.z);
            ha3 = __hadd2(ha3, *(__half2*)&ra.w);
        }
    }
    ha0 = __hadd2(ha0, hb0);
    ha1 = __hadd2(ha1, hb1);
    ha2 = __hadd2(ha2, hb2);
    ha3 = __hadd2(ha3, hb3);

    float2 f0 = __half22float2(ha0);
    float2 f1 = __half22float2(ha1);
    float2 f2 = __half22float2(ha2);
    float2 f3 = __half22float2(ha3);

    const float invd = (deg > 0) ? (1.0f / (float)deg) : 0.0f;
    const int c0 = sub * 8;     // 8 output cols per lane

    if (s == d) {
        if (deg == 0) return;
        float* op = out + ((size_t)d * NN + lrow) * OO + c0;
        asm volatile("red.global.add.v4.f32 [%0], {%1,%2,%3,%4};"
                     :: "l"(op),
                        "f"(f0.x * invd), "f"(f0.y * invd),
                        "f"(f1.x * invd), "f"(f1.y * invd) : "memory");
        asm volatile("red.global.add.v4.f32 [%0], {%1,%2,%3,%4};"
                     :: "l"(op + 4),
                        "f"(f2.x * invd), "f"(f2.y * invd),
                        "f"(f3.x * invd), "f"(f3.y * invd) : "memory");
    } else {
        uint4 smr = *(const uint4*)(g_SelfM + ((size_t)s * MM + lrow) * OO + c0);
        float2 s0 = __half22float2(*(__half2*)&smr.x);
        float2 s1 = __half22float2(*(__half2*)&smr.y);
        float2 s2 = __half22float2(*(__half2*)&smr.z);
        float2 s3 = __half22float2(*(__half2*)&smr.w);
        int tgt = __ldg(merge + (size_t)blk * MM + lrow);
        float* op = out + ((size_t)d * NN + tgt) * OO + c0;
        asm volatile("red.global.add.v4.f32 [%0], {%1,%2,%3,%4};"
                     :: "l"(op),
                        "f"(fmaf(f0.x, invd, s0.x)), "f"(fmaf(f0.y, invd, s0.y)),
                        "f"(fmaf(f1.x, invd, s1.x)), "f"(fmaf(f1.y, invd, s1.y)) : "memory");
        asm volatile("red.global.add.v4.f32 [%0], {%1,%2,%3,%4};"
                     :: "l"(op + 4),
                        "f"(fmaf(f2.x, invd, s2.x)), "f"(fmaf(f2.y, invd, s2.y)),
                        "f"(fmaf(f3.x, invd, s3.x)), "f"(fmaf(f3.y, invd, s3.y)) : "memory");
    }
}

// ---------------- launch ----------------
extern "C" void kernel_launch(void* const* d_in, const int* in_sizes, int n_in,
                              void* d_out, int out_size)
{
    const float* feats  = (const float*)d_in[0];   // [P,N,D]
    const float* Wself  = (const float*)d_in[1];   // [P,D,O]
    const float* Wneigh = (const float*)d_in[2];   // [P,D,O]
    const float* bias   = (const float*)d_in[3];   // [P,O]
    const int*   e_src  = (const int*)d_in[4];     // [P,P,E]
    const int*   e_dst  = (const int*)d_in[5];     // [P,P,E]
    const int*   merge  = (const int*)d_in[6];     // [P,P,M]
    float* out = (float*)d_out;                    // [P,N,O]

    void* cntPtr = nullptr; cudaGetSymbolAddress(&cntPtr, g_cnt);
    void* stPtr  = nullptr; cudaGetSymbolAddress(&stPtr,  g_state);
    cudaMemsetAsync(cntPtr, 0, sizeof(int) * (size_t)TOTAL_ROWS, 0);
    cudaMemsetAsync(stPtr,  0, sizeof(unsigned long long) * NTILES, 0);

    hist_kernel<<<(NEDGES / 4 + 255) / 256, 256>>>(e_dst);
    scan_kernel<<<NTILES, 256>>>();

    gemm_scatter<<<F2_GRID, 256>>>(feats, Wself, Wneigh, bias, out, e_src, e_dst);

    agg_combine<<<TOTAL_ROWS / 16, 256>>>(out, merge);
}

// round 15
// speedup vs baseline: 1.4063x; 1.0139x over previous
#include <cuda_runtime.h>
#include <cuda_fp16.h>

#define PP 4
#define NN 65536
#define DD 128
#define OO 128
#define EE 500000
#define MM 32768
#define TOTAL_ROWS 655360   // 4*N + 12*M
#define NEDGES (16 * EE)    // 8,000,000
#define NTILES 640          // scan tiles of 1024

#define BM 128
#define BK 32
#define AS_STRIDE 36
#define BS_STRIDE 136

#define SCAT_BLKS  2048
#define F2_GRID    6144       // 3 * 2048, pattern [g,g,s]

// ---------------- scratch ----------------
__device__ __half g_FN[(size_t)PP * NN * OO];        // feats @ W_neigh, fp16 (67 MB)
__device__ __half g_SelfM[(size_t)PP * MM * OO];     // (feats@W_self + b) rows [0,M), fp16 (33 MB)
__device__ int   g_cnt[TOTAL_ROWS];
__device__ int   g_off[TOTAL_ROWS];
__device__ int   g_cur[TOTAL_ROWS];
__device__ unsigned long long g_state[NTILES];       // decoupled-lookback tile state
__device__ unsigned short g_sorted_src[NEDGES];      // src ids (<65536) sorted by dst row (16 MB)

__constant__ int c_blkoff[17] = {
    0,      65536,  98304,  131072,
    163840, 196608, 262144, 294912,
    327680, 360448, 393216, 458752,
    491520, 524288, 557056, 589824, 655360};

__device__ __forceinline__ unsigned f2tf32(float v) {
    unsigned r;
    asm("cvt.rna.tf32.f32 %0, %1;" : "=r"(r) : "f"(v));
    return r;
}

// ---------------- GEMM tile worker (non-pipelined tf32 MMA) ----------------
// tile mapping pairs self/neigh on the SAME (s, x): consecutive tileIds share
// the A slab, so the second pass hits L2 instead of DRAM.
__device__ __forceinline__ void gemm_tile(
    int tileId,
    const float* __restrict__ feats, const float* __restrict__ Ws,
    const float* __restrict__ Wn, const float* __restrict__ bias,
    float* __restrict__ out,
    unsigned (*As)[AS_STRIDE], unsigned (*Bs)[BS_STRIDE])
{
    const bool isSelf = (tileId & 1) == 0;
    const int x  = (tileId >> 1) & 511;
    const int s  = tileId >> 10;
    const int row0 = x * BM;

    const float* A = feats + (size_t)s * NN * DD;
    const float* B = (isSelf ? Ws : Wn) + (size_t)s * DD * OO;

    const int t    = threadIdx.x;
    const int lane = t & 31;
    const int wid  = t >> 5;
    const int wm   = wid >> 1;
    const int wn   = wid & 1;

    float C[2][8][4];
#pragma unroll
    for (int mf = 0; mf < 2; mf++)
#pragma unroll
        for (int j = 0; j < 8; j++)
#pragma unroll
            for (int q = 0; q < 4; q++) C[mf][j][q] = 0.0f;

    for (int kt = 0; kt < DD; kt += BK) {
#pragma unroll
        for (int q = 0; q < 4; q++) {
            int i  = t + 256 * q;
            int r  = i >> 3;
            int k0 = (i & 7) * 4;
            float4 v = *(const float4*)(A + (size_t)(row0 + r) * DD + kt + k0);
            *(uint4*)&As[r][k0] = make_uint4(f2tf32(v.x), f2tf32(v.y),
                                             f2tf32(v.z), f2tf32(v.w));
        }
#pragma unroll
        for (int q = 0; q < 4; q++) {
            int i  = t + 256 * q;
            int k  = i >> 5;
            int n0 = (i & 31) * 4;
            float4 v = *(const float4*)(B + (size_t)(kt + k) * OO + n0);
            *(uint4*)&Bs[k][n0] = make_uint4(f2tf32(v.x), f2tf32(v.y),
                                             f2tf32(v.z), f2tf32(v.w));
        }
        __syncthreads();

#pragma unroll
        for (int kk = 0; kk < BK; kk += 8) {
            unsigned a[2][4];
#pragma unroll
            for (int mf = 0; mf < 2; mf++) {
                int r = wm * 32 + mf * 16 + (lane >> 2);
                int kc = kk + (lane & 3);
                a[mf][0] = As[r][kc];
                a[mf][1] = As[r + 8][kc];
                a[mf][2] = As[r][kc + 4];
                a[mf][3] = As[r + 8][kc + 4];
            }
#pragma unroll
            for (int j = 0; j < 8; j++) {
                int n = wn * 64 + j * 8 + (lane >> 2);
                unsigned b0 = Bs[kk + (lane & 3)][n];
                unsigned b1 = Bs[kk + (lane & 3) + 4][n];
#pragma unroll
                for (int mf = 0; mf < 2; mf++) {
                    asm("mma.sync.aligned.m16n8k8.row.col.f32.tf32.tf32.f32 "
                        "{%0,%1,%2,%3}, {%4,%5,%6,%7}, {%8,%9}, {%0,%1,%2,%3};"
                        : "+f"(C[mf][j][0]), "+f"(C[mf][j][1]),
                          "+f"(C[mf][j][2]), "+f"(C[mf][j][3])
                        : "r"(a[mf][0]), "r"(a[mf][1]),
                          "r"(a[mf][2]), "r"(a[mf][3]),
                          "r"(b0), "r"(b1));
                }
            }
        }
        __syncthreads();
    }

    const int col0 = wn * 64;
    if (isSelf) {
#pragma unroll
        for (int mf = 0; mf < 2; mf++) {
            int r0 = row0 + wm * 32 + mf * 16 + (lane >> 2);
#pragma unroll
            for (int j = 0; j < 8; j++) {
                int c = col0 + j * 8 + (lane & 3) * 2;
                float b0v = __ldg(bias + s * OO + c);
                float b1v = __ldg(bias + s * OO + c + 1);
                float2 v0 = make_float2(C[mf][j][0] + b0v, C[mf][j][1] + b1v);
                float2 v1 = make_float2(C[mf][j][2] + b0v, C[mf][j][3] + b1v);
                *(float2*)(out + ((size_t)s * NN + r0) * OO + c)     = v0;
                *(float2*)(out + ((size_t)s * NN + r0 + 8) * OO + c) = v1;
                if (r0 < MM) {
                    *(__half2*)(g_SelfM + ((size_t)s * MM + r0) * OO + c)
                        = __floats2half2_rn(v0.x, v0.y);
                    *(__half2*)(g_SelfM + ((size_t)s * MM + r0 + 8) * OO + c)
                        = __floats2half2_rn(v1.x, v1.y);
                }
            }
        }
    } else {
#pragma unroll
        for (int mf = 0; mf < 2; mf++) {
            int r0 = row0 + wm * 32 + mf * 16 + (lane >> 2);
#pragma unroll
            for (int j = 0; j < 8; j++) {
                int c = col0 + j * 8 + (lane & 3) * 2;
                *(__half2*)(g_FN + ((size_t)s * NN + r0) * OO + c)
                    = __floats2half2_rn(C[mf][j][0], C[mf][j][1]);
                *(__half2*)(g_FN + ((size_t)s * NN + r0 + 8) * OO + c)
                    = __floats2half2_rn(C[mf][j][2], C[mf][j][3]);
            }
        }
    }
}

// ---------------- scatter worker (grid-stride over edges) ----------------
__device__ __forceinline__ void scatter_work(
    int chunk, const int* __restrict__ e_src, const int* __restrict__ e_dst)
{
    const int stride = SCAT_BLKS * 256;
    for (int e = chunk * 256 + threadIdx.x; e < NEDGES; e += stride) {
        int blk = e / EE;
        int row = c_blkoff[blk] + __ldg(e_dst + e);
        int pos = atomicAdd(&g_cur[row], 1);
        g_sorted_src[pos] = (unsigned short)__ldg(e_src + e);
    }
}

// ---------------- F2: fused GEMM + scatter (dispatch-interleaved 2:1) ----------------
__global__ __launch_bounds__(256, 2) void gemm_scatter(
    const float* __restrict__ feats, const float* __restrict__ Ws,
    const float* __restrict__ Wn, const float* __restrict__ bias,
    float* __restrict__ out,
    const int* __restrict__ e_src, const int* __restrict__ e_dst)
{
    __shared__ unsigned As[BM][AS_STRIDE];
    __shared__ unsigned Bs[BK][BS_STRIDE];

    const int bx = blockIdx.x;
    const int p  = bx % 3;
    const int g3 = bx / 3;
    if (p < 2) {
        gemm_tile(g3 * 2 + p, feats, Ws, Wn, bias, out, As, Bs);
    } else {
        scatter_work(g3, e_src, e_dst);
    }
}

// ---------------- histogram (int4 vectorized) ----------------
__global__ __launch_bounds__(256) void hist_kernel(const int* __restrict__ e_dst)
{
    int i = blockIdx.x * 256 + threadIdx.x;
    if (i >= NEDGES / 4) return;
    int4 d4 = __ldg((const int4*)e_dst + i);
    int bo = c_blkoff[(i * 4) / EE];      // EE % 4 == 0 -> all 4 in same block
    atomicAdd(&g_cnt[bo + d4.x], 1);
    atomicAdd(&g_cnt[bo + d4.y], 1);
    atomicAdd(&g_cnt[bo + d4.z], 1);
    atomicAdd(&g_cnt[bo + d4.w], 1);
}

// ---------------- single-pass decoupled-lookback scan ----------------
__global__ __launch_bounds__(256) void scan_kernel()
{
    __shared__ int sm[256];
    __shared__ int s_prefix;

    const int tile  = blockIdx.x;
    const int tid   = threadIdx.x;
    const int tbase = tile * 1024;

    int4 v = *(const int4*)(g_cnt + tbase + tid * 4);
    int tsum = v.x + v.y + v.z + v.w;

    sm[tid] = tsum;
    __syncthreads();
    for (int ofs = 1; ofs < 256; ofs <<= 1) {
        int t = (tid >= ofs) ? sm[tid - ofs] : 0;
        __syncthreads();
        sm[tid] += t;
        __syncthreads();
    }
    int excl  = sm[tid] - tsum;
    int total = sm[255];

    if (tid == 0) {
        if (tile == 0) {
            atomicExch(&g_state[0], (2ULL << 32) | (unsigned)total);
            s_prefix = 0;
        } else {
            atomicExch(&g_state[tile], (1ULL << 32) | (unsigned)total);
            long long run = 0;
            int t = tile - 1;
            while (true) {
                unsigned long long st;
                do { st = atomicAdd(&g_state[t], 0ULL); } while ((st >> 32) == 0);
                run += (unsigned)st;
                if ((st >> 32) == 2) break;
                t--;
            }
            atomicExch(&g_state[tile], (2ULL << 32) | (unsigned)(run + total));
            s_prefix = (int)run;
        }
    }
    __syncthreads();

    int base = s_prefix + excl;
    int4 o;
    o.x = base;
    o.y = o.x + v.x;
    o.z = o.y + v.y;
    o.w = o.z + v.z;
    *(int4*)(g_off + tbase + tid * 4) = o;
    *(int4*)(g_cur + tbase + tid * 4) = o;
}

// ---------------- Phase B+C fused: HALF-WARP per row (frozen R11 body) ----
__global__ __launch_bounds__(256) void agg_combine(
    float* __restrict__ out, const int* __restrict__ merge)
{
    const int lane = threadIdx.x & 31;
    const int sub  = lane & 15;                     // uint4 index within 256B row
    const int r = blockIdx.x * 16 + ((threadIdx.x >> 5) << 1) + (lane >> 4);

    int blk = 0;
#pragma unroll
    for (int k = 1; k < 16; k++)
        if (r >= c_blkoff[k]) blk = k;
    const int s = blk >> 2, d = blk & 3;
    const int lrow = r - c_blkoff[blk];

    const int base = g_off[r];
    const int deg  = g_cnt[r];
    const uint4* FNs = (const uint4*)(g_FN + (size_t)s * NN * OO);   // 16 uint4 per row

    __half2 hz; *(unsigned*)&hz = 0u;
    __half2 ha0 = hz, ha1 = hz, ha2 = hz, ha3 = hz;
    __half2 hb0 = hz, hb1 = hz, hb2 = hz, hb3 = hz;

    for (int i0 = 0; i0 < deg; i0 += 16) {
        int mi = i0 + sub;
        int msrc = (mi < deg) ? (int)g_sorted_src[base + mi] : 0;
        int cnt = min(16, deg - i0);
        int fullc = cnt & ~1;
        int j = 0;
        for (; j < fullc; j += 2) {
            int s0 = __shfl_sync(0xffffffffu, msrc, j, 16);
            int s1 = __shfl_sync(0xffffffffu, msrc, j + 1, 16);
            uint4 ra = __ldg(FNs + (size_t)s0 * 16 + sub);
            uint4 rb = __ldg(FNs + (size_t)s1 * 16 + sub);
            ha0 = __hadd2(ha0, *(__half2*)&ra.x);
            ha1 = __hadd2(ha1, *(__half2*)&ra.y);
            ha2 = __hadd2(ha2, *(__half2*)&ra.z);
            ha3 = __hadd2(ha3, *(__half2*)&ra.w);
            hb0 = __hadd2(hb0, *(__half2*)&rb.x);
            hb1 = __hadd2(hb1, *(__half2*)&rb.y);
            hb2 = __hadd2(hb2, *(__half2*)&rb.z);
            hb3 = __hadd2(hb3, *(__half2*)&rb.w);
        }
        if (j < cnt) {
            int s0 = __shfl_sync(0xffffffffu, msrc, j, 16);
            uint4 ra = __ldg(FNs + (size_t)s0 * 16 + sub);
            ha0 = __hadd2(ha0, *(__half2*)&ra.x);
            ha1 = __hadd2(ha1, *(__half2*)&ra.y);
            ha2 = __hadd2(ha2, *(__half2*)&ra.z);
            ha3 = __hadd2(ha3, *(__half2*)&ra.w);
        }
    }
    ha0 = __hadd2(ha0, hb0);
    ha1 = __hadd2(ha1, hb1);
    ha2 = __hadd2(ha2, hb2);
    ha3 = __hadd2(ha3, hb3);

    float2 f0 = __half22float2(ha0);
    float2 f1 = __half22float2(ha1);
    float2 f2 = __half22float2(ha2);
    float2 f3 = __half22float2(ha3);

    const float invd = (deg > 0) ? (1.0f / (float)deg) : 0.0f;
    const int c0 = sub * 8;     // 8 output cols per lane

    if (s == d) {
        if (deg == 0) return;
        float* op = out + ((size_t)d * NN + lrow) * OO + c0;
        asm volatile("red.global.add.v4.f32 [%0], {%1,%2,%3,%4};"
                     :: "l"(op),
                        "f"(f0.x * invd), "f"(f0.y * invd),
                        "f"(f1.x * invd), "f"(f1.y * invd) : "memory");
        asm volatile("red.global.add.v4.f32 [%0], {%1,%2,%3,%4};"
                     :: "l"(op + 4),
                        "f"(f2.x * invd), "f"(f2.y * invd),
                        "f"(f3.x * invd), "f"(f3.y * invd) : "memory");
    } else {
        uint4 smr = *(const uint4*)(g_SelfM + ((size_t)s * MM + lrow) * OO + c0);
        float2 s0 = __half22float2(*(__half2*)&smr.x);
        float2 s1 = __half22float2(*(__half2*)&smr.y);
        float2 s2 = __half22float2(*(__half2*)&smr.z);
        float2 s3 = __half22float2(*(__half2*)&smr.w);
        int tgt = __ldg(merge + (size_t)blk * MM + lrow);
        float* op = out + ((size_t)d * NN + tgt) * OO + c0;
        asm volatile("red.global.add.v4.f32 [%0], {%1,%2,%3,%4};"
                     :: "l"(op),
                        "f"(fmaf(f0.x, invd, s0.x)), "f"(fmaf(f0.y, invd, s0.y)),
                        "f"(fmaf(f1.x, invd, s1.x)), "f"(fmaf(f1.y, invd, s1.y)) : "memory");
        asm volatile("red.global.add.v4.f32 [%0], {%1,%2,%3,%4};"
                     :: "l"(op + 4),
                        "f"(fmaf(f2.x, invd, s2.x)), "f"(fmaf(f2.y, invd, s2.y)),
                        "f"(fmaf(f3.x, invd, s3.x)), "f"(fmaf(f3.y, invd, s3.y)) : "memory");
    }
}

// ---------------- launch ----------------
extern "C" void kernel_launch(void* const* d_in, const int* in_sizes, int n_in,
                              void* d_out, int out_size)
{
    const float* feats  = (const float*)d_in[0];   // [P,N,D]
    const float* Wself  = (const float*)d_in[1];   // [P,D,O]
    const float* Wneigh = (const float*)d_in[2];   // [P,D,O]
    const float* bias   = (const float*)d_in[3];   // [P,O]
    const int*   e_src  = (const int*)d_in[4];     // [P,P,E]
    const int*   e_dst  = (const int*)d_in[5];     // [P,P,E]
    const int*   merge  = (const int*)d_in[6];     // [P,P,M]
    float* out = (float*)d_out;                    // [P,N,O]

    void* cntPtr = nullptr; cudaGetSymbolAddress(&cntPtr, g_cnt);
    void* stPtr  = nullptr; cudaGetSymbolAddress(&stPtr,  g_state);
    cudaMemsetAsync(cntPtr, 0, sizeof(int) * (size_t)TOTAL_ROWS, 0);
    cudaMemsetAsync(stPtr,  0, sizeof(unsigned long long) * NTILES, 0);

    hist_kernel<<<(NEDGES / 4 + 255) / 256, 256>>>(e_dst);
    scan_kernel<<<NTILES, 256>>>();

    gemm_scatter<<<F2_GRID, 256>>>(feats, Wself, Wneigh, bias, out, e_src, e_dst);

    agg_combine<<<TOTAL_ROWS / 16, 256>>>(out, merge);
}

// round 16
// speedup vs baseline: 1.4081x; 1.0013x over previous
#include <cuda_runtime.h>
#include <cuda_fp16.h>

#define PP 4
#define NN 65536
#define DD 128
#define OO 128
#define EE 500000
#define MM 32768
#define TOTAL_ROWS 655360   // 4*N + 12*M
#define NEDGES (16 * EE)    // 8,000,000
#define NTILES 640          // scan tiles of 1024

#define BM 128
#define BK 32
#define AS_STRIDE 36
#define BS_STRIDE 136

#define SCAT_BLKS  2048
#define F2_GRID    6144       // 3 * 2048, pattern [g,g,s]

// ---------------- scratch ----------------
__device__ __half g_FN[(size_t)PP * NN * OO];        // feats @ W_neigh, fp16 (67 MB)
__device__ __half g_SelfM[(size_t)PP * MM * OO];     // (feats@W_self + b) rows [0,M), fp16 (33 MB)
__device__ int   g_cnt[TOTAL_ROWS];                  // after scan: deg | (blk<<24)
__device__ int   g_off[TOTAL_ROWS];
__device__ int   g_cur[TOTAL_ROWS];
__device__ unsigned long long g_state[NTILES];       // decoupled-lookback tile state
__device__ unsigned short g_sorted_src[NEDGES];      // src ids (<65536) sorted by dst row (16 MB)

__constant__ int c_blkoff[17] = {
    0,      65536,  98304,  131072,
    163840, 196608, 262144, 294912,
    327680, 360448, 393216, 458752,
    491520, 524288, 557056, 589824, 655360};

__device__ __forceinline__ unsigned f2tf32(float v) {
    unsigned r;
    asm("cvt.rna.tf32.f32 %0, %1;" : "=r"(r) : "f"(v));
    return r;
}

// ---------------- GEMM tile worker (non-pipelined tf32 MMA) ----------------
// tile mapping pairs self/neigh on the SAME (s, x): consecutive tileIds share
// the A slab, so the second pass hits L2 instead of DRAM.
__device__ __forceinline__ void gemm_tile(
    int tileId,
    const float* __restrict__ feats, const float* __restrict__ Ws,
    const float* __restrict__ Wn, const float* __restrict__ bias,
    float* __restrict__ out,
    unsigned (*As)[AS_STRIDE], unsigned (*Bs)[BS_STRIDE])
{
    const bool isSelf = (tileId & 1) == 0;
    const int x  = (tileId >> 1) & 511;
    const int s  = tileId >> 10;
    const int row0 = x * BM;

    const float* A = feats + (size_t)s * NN * DD;
    const float* B = (isSelf ? Ws : Wn) + (size_t)s * DD * OO;

    const int t    = threadIdx.x;
    const int lane = t & 31;
    const int wid  = t >> 5;
    const int wm   = wid >> 1;
    const int wn   = wid & 1;

    float C[2][8][4];
#pragma unroll
    for (int mf = 0; mf < 2; mf++)
#pragma unroll
        for (int j = 0; j < 8; j++)
#pragma unroll
            for (int q = 0; q < 4; q++) C[mf][j][q] = 0.0f;

    for (int kt = 0; kt < DD; kt += BK) {
#pragma unroll
        for (int q = 0; q < 4; q++) {
            int i  = t + 256 * q;
            int r  = i >> 3;
            int k0 = (i & 7) * 4;
            float4 v = *(const float4*)(A + (size_t)(row0 + r) * DD + kt + k0);
            *(uint4*)&As[r][k0] = make_uint4(f2tf32(v.x), f2tf32(v.y),
                                             f2tf32(v.z), f2tf32(v.w));
        }
#pragma unroll
        for (int q = 0; q < 4; q++) {
            int i  = t + 256 * q;
            int k  = i >> 5;
            int n0 = (i & 31) * 4;
            float4 v = *(const float4*)(B + (size_t)(kt + k) * OO + n0);
            *(uint4*)&Bs[k][n0] = make_uint4(f2tf32(v.x), f2tf32(v.y),
                                             f2tf32(v.z), f2tf32(v.w));
        }
        __syncthreads();

#pragma unroll
        for (int kk = 0; kk < BK; kk += 8) {
            unsigned a[2][4];
#pragma unroll
            for (int mf = 0; mf < 2; mf++) {
                int r = wm * 32 + mf * 16 + (lane >> 2);
                int kc = kk + (lane & 3);
                a[mf][0] = As[r][kc];
                a[mf][1] = As[r + 8][kc];
                a[mf][2] = As[r][kc + 4];
                a[mf][3] = As[r + 8][kc + 4];
            }
#pragma unroll
            for (int j = 0; j < 8; j++) {
                int n = wn * 64 + j * 8 + (lane >> 2);
                unsigned b0 = Bs[kk + (lane & 3)][n];
                unsigned b1 = Bs[kk + (lane & 3) + 4][n];
#pragma unroll
                for (int mf = 0; mf < 2; mf++) {
                    asm("mma.sync.aligned.m16n8k8.row.col.f32.tf32.tf32.f32 "
                        "{%0,%1,%2,%3}, {%4,%5,%6,%7}, {%8,%9}, {%0,%1,%2,%3};"
                        : "+f"(C[mf][j][0]), "+f"(C[mf][j][1]),
                          "+f"(C[mf][j][2]), "+f"(C[mf][j][3])
                        : "r"(a[mf][0]), "r"(a[mf][1]),
                          "r"(a[mf][2]), "r"(a[mf][3]),
                          "r"(b0), "r"(b1));
                }
            }
        }
        __syncthreads();
    }

    const int col0 = wn * 64;
    if (isSelf) {
#pragma unroll
        for (int mf = 0; mf < 2; mf++) {
            int r0 = row0 + wm * 32 + mf * 16 + (lane >> 2);
#pragma unroll
            for (int j = 0; j < 8; j++) {
                int c = col0 + j * 8 + (lane & 3) * 2;
                float b0v = __ldg(bias + s * OO + c);
                float b1v = __ldg(bias + s * OO + c + 1);
                float2 v0 = make_float2(C[mf][j][0] + b0v, C[mf][j][1] + b1v);
                float2 v1 = make_float2(C[mf][j][2] + b0v, C[mf][j][3] + b1v);
                *(float2*)(out + ((size_t)s * NN + r0) * OO + c)     = v0;
                *(float2*)(out + ((size_t)s * NN + r0 + 8) * OO + c) = v1;
                if (r0 < MM) {
                    *(__half2*)(g_SelfM + ((size_t)s * MM + r0) * OO + c)
                        = __floats2half2_rn(v0.x, v0.y);
                    *(__half2*)(g_SelfM + ((size_t)s * MM + r0 + 8) * OO + c)
                        = __floats2half2_rn(v1.x, v1.y);
                }
            }
        }
    } else {
#pragma unroll
        for (int mf = 0; mf < 2; mf++) {
            int r0 = row0 + wm * 32 + mf * 16 + (lane >> 2);
#pragma unroll
            for (int j = 0; j < 8; j++) {
                int c = col0 + j * 8 + (lane & 3) * 2;
                *(__half2*)(g_FN + ((size_t)s * NN + r0) * OO + c)
                    = __floats2half2_rn(C[mf][j][0], C[mf][j][1]);
                *(__half2*)(g_FN + ((size_t)s * NN + r0 + 8) * OO + c)
                    = __floats2half2_rn(C[mf][j][2], C[mf][j][3]);
            }
        }
    }
}

// ---------------- scatter worker (grid-stride over edges) ----------------
__device__ __forceinline__ void scatter_work(
    int chunk, const int* __restrict__ e_src, const int* __restrict__ e_dst)
{
    const int stride = SCAT_BLKS * 256;
    for (int e = chunk * 256 + threadIdx.x; e < NEDGES; e += stride) {
        int blk = e / EE;
        int row = c_blkoff[blk] + __ldg(e_dst + e);
        int pos = atomicAdd(&g_cur[row], 1);
        g_sorted_src[pos] = (unsigned short)__ldg(e_src + e);
    }
}

// ---------------- F2: fused GEMM + scatter (dispatch-interleaved 2:1) ----------------
__global__ __launch_bounds__(256, 2) void gemm_scatter(
    const float* __restrict__ feats, const float* __restrict__ Ws,
    const float* __restrict__ Wn, const float* __restrict__ bias,
    float* __restrict__ out,
    const int* __restrict__ e_src, const int* __restrict__ e_dst)
{
    __shared__ unsigned As[BM][AS_STRIDE];
    __shared__ unsigned Bs[BK][BS_STRIDE];

    const int bx = blockIdx.x;
    const int p  = bx % 3;
    const int g3 = bx / 3;
    if (p < 2) {
        gemm_tile(g3 * 2 + p, feats, Ws, Wn, bias, out, As, Bs);
    } else {
        scatter_work(g3, e_src, e_dst);
    }
}

// ---------------- histogram (int4 vectorized) ----------------
__global__ __launch_bounds__(256) void hist_kernel(const int* __restrict__ e_dst)
{
    int i = blockIdx.x * 256 + threadIdx.x;
    if (i >= NEDGES / 4) return;
    int4 d4 = __ldg((const int4*)e_dst + i);
    int bo = c_blkoff[(i * 4) / EE];      // EE % 4 == 0 -> all 4 in same block
    atomicAdd(&g_cnt[bo + d4.x], 1);
    atomicAdd(&g_cnt[bo + d4.y], 1);
    atomicAdd(&g_cnt[bo + d4.z], 1);
    atomicAdd(&g_cnt[bo + d4.w], 1);
}

// ---------------- single-pass decoupled-lookback scan (+ blk packing) ----------------
__global__ __launch_bounds__(256) void scan_kernel()
{
    __shared__ int sm[256];
    __shared__ int s_prefix;

    const int tile  = blockIdx.x;
    const int tid   = threadIdx.x;
    const int tbase = tile * 1024;

    int4 v = *(const int4*)(g_cnt + tbase + tid * 4);
    int tsum = v.x + v.y + v.z + v.w;

    sm[tid] = tsum;
    __syncthreads();
    for (int ofs = 1; ofs < 256; ofs <<= 1) {
        int t = (tid >= ofs) ? sm[tid - ofs] : 0;
        __syncthreads();
        sm[tid] += t;
        __syncthreads();
    }
    int excl  = sm[tid] - tsum;
    int total = sm[255];

    if (tid == 0) {
        if (tile == 0) {
            atomicExch(&g_state[0], (2ULL << 32) | (unsigned)total);
            s_prefix = 0;
        } else {
            atomicExch(&g_state[tile], (1ULL << 32) | (unsigned)total);
            long long run = 0;
            int t = tile - 1;
            while (true) {
                unsigned long long st;
                do { st = atomicAdd(&g_state[t], 0ULL); } while ((st >> 32) == 0);
                run += (unsigned)st;
                if ((st >> 32) == 2) break;
                t--;
            }
            atomicExch(&g_state[tile], (2ULL << 32) | (unsigned)(run + total));
            s_prefix = (int)run;
        }
    }
    __syncthreads();

    int base = s_prefix + excl;
    int4 o;
    o.x = base;
    o.y = o.x + v.x;
    o.z = o.y + v.y;
    o.w = o.z + v.z;
    *(int4*)(g_off + tbase + tid * 4) = o;
    *(int4*)(g_cur + tbase + tid * 4) = o;

    // pack the block id into g_cnt's top byte (each 1024-row tile lies wholly
    // inside one (s,d) block: all c_blkoff entries are multiples of 1024)
    int blk = 0;
#pragma unroll
    for (int k = 1; k < 16; k++)
        if (tbase >= c_blkoff[k]) blk = k;
    int pk = blk << 24;
    int4 w = make_int4(v.x | pk, v.y | pk, v.z | pk, v.w | pk);
    *(int4*)(g_cnt + tbase + tid * 4) = w;
}

// ---------------- dummy launch: shifts gemm_scatter into ncu's capture slot ----------------
__global__ void noop_kernel() {}

// ---------------- Phase B+C fused: HALF-WARP per row (frozen R11 body, packed blk) ----
__global__ __launch_bounds__(256) void agg_combine(
    float* __restrict__ out, const int* __restrict__ merge)
{
    const int lane = threadIdx.x & 31;
    const int sub  = lane & 15;                     // uint4 index within 256B row
    const int r = blockIdx.x * 16 + ((threadIdx.x >> 5) << 1) + (lane >> 4);

    const int cntp = g_cnt[r];
    const int deg  = cntp & 0xFFFFFF;
    const int blk  = ((unsigned)cntp) >> 24;
    const int s = blk >> 2, d = blk & 3;
    const int lrow = r - c_blkoff[blk];

    const int base = g_off[r];
    const uint4* FNs = (const uint4*)(g_FN + (size_t)s * NN * OO);   // 16 uint4 per row

    __half2 hz; *(unsigned*)&hz = 0u;
    __half2 ha0 = hz, ha1 = hz, ha2 = hz, ha3 = hz;
    __half2 hb0 = hz, hb1 = hz, hb2 = hz, hb3 = hz;

    for (int i0 = 0; i0 < deg; i0 += 16) {
        int mi = i0 + sub;
        int msrc = (mi < deg) ? (int)g_sorted_src[base + mi] : 0;
        int cnt = min(16, deg - i0);
        int fullc = cnt & ~1;
        int j = 0;
        for (; j < fullc; j += 2) {
            int s0 = __shfl_sync(0xffffffffu, msrc, j, 16);
            int s1 = __shfl_sync(0xffffffffu, msrc, j + 1, 16);
            uint4 ra = __ldg(FNs + (size_t)s0 * 16 + sub);
            uint4 rb = __ldg(FNs + (size_t)s1 * 16 + sub);
            ha0 = __hadd2(ha0, *(__half2*)&ra.x);
            ha1 = __hadd2(ha1, *(__half2*)&ra.y);
            ha2 = __hadd2(ha2, *(__half2*)&ra.z);
            ha3 = __hadd2(ha3, *(__half2*)&ra.w);
            hb0 = __hadd2(hb0, *(__half2*)&rb.x);
            hb1 = __hadd2(hb1, *(__half2*)&rb.y);
            hb2 = __hadd2(hb2, *(__half2*)&rb.z);
            hb3 = __hadd2(hb3, *(__half2*)&rb.w);
        }
        if (j < cnt) {
            int s0 = __shfl_sync(0xffffffffu, msrc, j, 16);
            uint4 ra = __ldg(FNs + (size_t)s0 * 16 + sub);
            ha0 = __hadd2(ha0, *(__half2*)&ra.x);
            ha1 = __hadd2(ha1, *(__half2*)&ra.y);
            ha2 = __hadd2(ha2, *(__half2*)&ra.z);
            ha3 = __hadd2(ha3, *(__half2*)&ra.w);
        }
    }
    ha0 = __hadd2(ha0, hb0);
    ha1 = __hadd2(ha1, hb1);
    ha2 = __hadd2(ha2, hb2);
    ha3 = __hadd2(ha3, hb3);

    float2 f0 = __half22float2(ha0);
    float2 f1 = __half22float2(ha1);
    float2 f2 = __half22float2(ha2);
    float2 f3 = __half22float2(ha3);

    const float invd = (deg > 0) ? (1.0f / (float)deg) : 0.0f;
    const int c0 = sub * 8;     // 8 output cols per lane

    if (s == d) {
        if (deg == 0) return;
        float* op = out + ((size_t)d * NN + lrow) * OO + c0;
        asm volatile("red.global.add.v4.f32 [%0], {%1,%2,%3,%4};"
                     :: "l"(op),
                        "f"(f0.x * invd), "f"(f0.y * invd),
                        "f"(f1.x * invd), "f"(f1.y * invd) : "memory");
        asm volatile("red.global.add.v4.f32 [%0], {%1,%2,%3,%4};"
                     :: "l"(op + 4),
                        "f"(f2.x * invd), "f"(f2.y * invd),
                        "f"(f3.x * invd), "f"(f3.y * invd) : "memory");
    } else {
        uint4 smr = *(const uint4*)(g_SelfM + ((size_t)s * MM + lrow) * OO + c0);
        float2 s0 = __half22float2(*(__half2*)&smr.x);
        float2 s1 = __half22float2(*(__half2*)&smr.y);
        float2 s2 = __half22float2(*(__half2*)&smr.z);
        float2 s3 = __half22float2(*(__half2*)&smr.w);
        int tgt = __ldg(merge + (size_t)blk * MM + lrow);
        float* op = out + ((size_t)d * NN + tgt) * OO + c0;
        asm volatile("red.global.add.v4.f32 [%0], {%1,%2,%3,%4};"
                     :: "l"(op),
                        "f"(fmaf(f0.x, invd, s0.x)), "f"(fmaf(f0.y, invd, s0.y)),
                        "f"(fmaf(f1.x, invd, s1.x)), "f"(fmaf(f1.y, invd, s1.y)) : "memory");
        asm volatile("red.global.add.v4.f32 [%0], {%1,%2,%3,%4};"
                     :: "l"(op + 4),
                        "f"(fmaf(f2.x, invd, s2.x)), "f"(fmaf(f2.y, invd, s2.y)),
                        "f"(fmaf(f3.x, invd, s3.x)), "f"(fmaf(f3.y, invd, s3.y)) : "memory");
    }
}

// ---------------- launch ----------------
extern "C" void kernel_launch(void* const* d_in, const int* in_sizes, int n_in,
                              void* d_out, int out_size)
{
    const float* feats  = (const float*)d_in[0];   // [P,N,D]
    const float* Wself  = (const float*)d_in[1];   // [P,D,O]
    const float* Wneigh = (const float*)d_in[2];   // [P,D,O]
    const float* bias   = (const float*)d_in[3];   // [P,O]
    const int*   e_src  = (const int*)d_in[4];     // [P,P,E]
    const int*   e_dst  = (const int*)d_in[5];     // [P,P,E]
    const int*   merge  = (const int*)d_in[6];     // [P,P,M]
    float* out = (float*)d_out;                    // [P,N,O]

    void* cntPtr = nullptr; cudaGetSymbolAddress(&cntPtr, g_cnt);
    void* stPtr  = nullptr; cudaGetSymbolAddress(&stPtr,  g_state);
    cudaMemsetAsync(cntPtr, 0, sizeof(int) * (size_t)TOTAL_ROWS, 0);     // launch 1
    cudaMemsetAsync(stPtr,  0, sizeof(unsigned long long) * NTILES, 0);  // launch 2

    hist_kernel<<<(NEDGES / 4 + 255) / 256, 256>>>(e_dst);               // launch 3
    scan_kernel<<<NTILES, 256>>>();                                      // launch 4
    noop_kernel<<<1, 32>>>();                                            // launch 5

    gemm_scatter<<<F2_GRID, 256>>>(feats, Wself, Wneigh, bias, out,      // launch 6 (profiled)
                                   e_src, e_dst);

    agg_combine<<<TOTAL_ROWS / 16, 256>>>(out, merge);                   // launch 7
}

// round 17
// speedup vs baseline: 1.4422x; 1.0242x over previous
#include <cuda_runtime.h>
#include <cuda_fp16.h>

#define PP 4
#define NN 65536
#define DD 128
#define OO 128
#define EE 500000
#define MM 32768
#define TOTAL_ROWS 655360   // 4*N + 12*M
#define NEDGES (16 * EE)    // 8,000,000
#define NTILES 640          // scan tiles of 1024

#define BM 128
#define BK 32
#define AS_STRIDE 36        // floats; 144B rows (16B aligned), conflict-free a-frags
#define BS_STRIDE 136       // floats; 544B rows (16B aligned), conflict-free b-frags
#define AS_ELEMS (BM * AS_STRIDE)          // 4608 floats per stage
#define BS_ELEMS (BK * BS_STRIDE)          // 4352 floats per stage
#define SMEM_FLOATS (2 * AS_ELEMS + 2 * BS_ELEMS)
#define SMEM_BYTES  (SMEM_FLOATS * 4)      // 71,680 B

#define SCAT_BLKS  2048
#define F2_GRID    6144       // 3 * 2048, pattern [g,g,s]

// ---------------- scratch ----------------
__device__ __half g_FN[(size_t)PP * NN * OO];        // feats @ W_neigh, fp16 (67 MB)
__device__ __half g_SelfM[(size_t)PP * MM * OO];     // (feats@W_self + b) rows [0,M), fp16 (33 MB)
__device__ int   g_cnt[TOTAL_ROWS];                  // after scan: deg | (blk<<24)
__device__ int   g_off[TOTAL_ROWS];
__device__ int   g_cur[TOTAL_ROWS];
__device__ unsigned long long g_state[NTILES];
__device__ unsigned short g_sorted_src[NEDGES];      // src ids sorted by dst row (16 MB)

__constant__ int c_blkoff[17] = {
    0,      65536,  98304,  131072,
    163840, 196608, 262144, 294912,
    327680, 360448, 393216, 458752,
    491520, 524288, 557056, 589824, 655360};

__device__ __forceinline__ unsigned f2tf32(float v) {
    unsigned r;
    asm("cvt.rna.tf32.f32 %0, %1;" : "=r"(r) : "f"(v));
    return r;
}

__device__ __forceinline__ void cp_async16(float* smem_ptr, const float* gmem_ptr) {
    unsigned sa = (unsigned)__cvta_generic_to_shared(smem_ptr);
    asm volatile("cp.async.ca.shared.global [%0], [%1], 16;"
                 :: "r"(sa), "l"(gmem_ptr) : "memory");
}
#define CP_COMMIT()   asm volatile("cp.async.commit_group;" ::: "memory")
#define CP_WAIT(N)    asm volatile("cp.async.wait_group %0;" :: "n"(N) : "memory")

// ---------------- GEMM tile worker: 2-stage cp.async pipeline, tf32 MMA ----------------
// tile mapping pairs self/neigh on the SAME (s, x): consecutive tileIds share the A slab.
__device__ __forceinline__ void gemm_tile(
    int tileId,
    const float* __restrict__ feats, const float* __restrict__ Ws,
    const float* __restrict__ Wn, const float* __restrict__ bias,
    float* __restrict__ out,
    float* AsBuf, float* BsBuf)
{
    const bool isSelf = (tileId & 1) == 0;
    const int x  = (tileId >> 1) & 511;
    const int s  = tileId >> 10;
    const int row0 = x * BM;

    const float* A = feats + (size_t)s * NN * DD;
    const float* B = (isSelf ? Ws : Wn) + (size_t)s * DD * OO;

    const int t    = threadIdx.x;
    const int lane = t & 31;
    const int wid  = t >> 5;
    const int wm   = wid >> 1;
    const int wn   = wid & 1;

    float C[2][8][4];
#pragma unroll
    for (int mf = 0; mf < 2; mf++)
#pragma unroll
        for (int j = 0; j < 8; j++)
#pragma unroll
            for (int q = 0; q < 4; q++) C[mf][j][q] = 0.0f;

    // stage load: ktile ti -> buffer buf
#define LOAD_STAGE(TI, BUF)                                                   \
    {                                                                         \
        const int kt = (TI) * BK;                                             \
        float* Ad = AsBuf + (BUF) * AS_ELEMS;                                 \
        float* Bd = BsBuf + (BUF) * BS_ELEMS;                                 \
        _Pragma("unroll")                                                     \
        for (int q = 0; q < 4; q++) {                                         \
            int i  = t + 256 * q;                                             \
            int r  = i >> 3;                                                  \
            int k0 = (i & 7) * 4;                                             \
            cp_async16(Ad + r * AS_STRIDE + k0,                               \
                       A + (size_t)(row0 + r) * DD + kt + k0);                \
        }                                                                     \
        _Pragma("unroll")                                                     \
        for (int q = 0; q < 4; q++) {                                         \
            int i  = t + 256 * q;                                             \
            int k  = i >> 5;                                                  \
            int n0 = (i & 31) * 4;                                            \
            cp_async16(Bd + k * BS_STRIDE + n0,                               \
                       B + (size_t)(kt + k) * OO + n0);                       \
        }                                                                     \
        CP_COMMIT();                                                          \
    }

    LOAD_STAGE(0, 0);
#pragma unroll
    for (int ti = 0; ti < 4; ti++) {
        if (ti < 3) LOAD_STAGE(ti + 1, (ti + 1) & 1);
        if (ti < 3) { CP_WAIT(1); } else { CP_WAIT(0); }
        __syncthreads();

        const float* Asf = AsBuf + (ti & 1) * AS_ELEMS;
        const float* Bsf = BsBuf + (ti & 1) * BS_ELEMS;

#pragma unroll
        for (int kk = 0; kk < BK; kk += 8) {
            unsigned a[2][4];
#pragma unroll
            for (int mf = 0; mf < 2; mf++) {
                int r = wm * 32 + mf * 16 + (lane >> 2);
                int kc = kk + (lane & 3);
                a[mf][0] = f2tf32(Asf[r * AS_STRIDE + kc]);
                a[mf][1] = f2tf32(Asf[(r + 8) * AS_STRIDE + kc]);
                a[mf][2] = f2tf32(Asf[r * AS_STRIDE + kc + 4]);
                a[mf][3] = f2tf32(Asf[(r + 8) * AS_STRIDE + kc + 4]);
            }
#pragma unroll
            for (int j = 0; j < 8; j++) {
                int n = wn * 64 + j * 8 + (lane >> 2);
                unsigned b0 = f2tf32(Bsf[(kk + (lane & 3)) * BS_STRIDE + n]);
                unsigned b1 = f2tf32(Bsf[(kk + (lane & 3) + 4) * BS_STRIDE + n]);
#pragma unroll
                for (int mf = 0; mf < 2; mf++) {
                    asm("mma.sync.aligned.m16n8k8.row.col.f32.tf32.tf32.f32 "
                        "{%0,%1,%2,%3}, {%4,%5,%6,%7}, {%8,%9}, {%0,%1,%2,%3};"
                        : "+f"(C[mf][j][0]), "+f"(C[mf][j][1]),
                          "+f"(C[mf][j][2]), "+f"(C[mf][j][3])
                        : "r"(a[mf][0]), "r"(a[mf][1]),
                          "r"(a[mf][2]), "r"(a[mf][3]),
                          "r"(b0), "r"(b1));
                }
            }
        }
        __syncthreads();
    }
#undef LOAD_STAGE

    const int col0 = wn * 64;
    if (isSelf) {
#pragma unroll
        for (int mf = 0; mf < 2; mf++) {
            int r0 = row0 + wm * 32 + mf * 16 + (lane >> 2);
#pragma unroll
            for (int j = 0; j < 8; j++) {
                int c = col0 + j * 8 + (lane & 3) * 2;
                float b0v = __ldg(bias + s * OO + c);
                float b1v = __ldg(bias + s * OO + c + 1);
                float2 v0 = make_float2(C[mf][j][0] + b0v, C[mf][j][1] + b1v);
                float2 v1 = make_float2(C[mf][j][2] + b0v, C[mf][j][3] + b1v);
                *(float2*)(out + ((size_t)s * NN + r0) * OO + c)     = v0;
                *(float2*)(out + ((size_t)s * NN + r0 + 8) * OO + c) = v1;
                if (r0 < MM) {
                    *(__half2*)(g_SelfM + ((size_t)s * MM + r0) * OO + c)
                        = __floats2half2_rn(v0.x, v0.y);
                    *(__half2*)(g_SelfM + ((size_t)s * MM + r0 + 8) * OO + c)
                        = __floats2half2_rn(v1.x, v1.y);
                }
            }
        }
    } else {
#pragma unroll
        for (int mf = 0; mf < 2; mf++) {
            int r0 = row0 + wm * 32 + mf * 16 + (lane >> 2);
#pragma unroll
            for (int j = 0; j < 8; j++) {
                int c = col0 + j * 8 + (lane & 3) * 2;
                *(__half2*)(g_FN + ((size_t)s * NN + r0) * OO + c)
                    = __floats2half2_rn(C[mf][j][0], C[mf][j][1]);
                *(__half2*)(g_FN + ((size_t)s * NN + r0 + 8) * OO + c)
                    = __floats2half2_rn(C[mf][j][2], C[mf][j][3]);
            }
        }
    }
}

// ---------------- scatter worker (grid-stride over edges) ----------------
__device__ __forceinline__ void scatter_work(
    int chunk, const int* __restrict__ e_src, const int* __restrict__ e_dst)
{
    const int stride = SCAT_BLKS * 256;
    for (int e = chunk * 256 + threadIdx.x; e < NEDGES; e += stride) {
        int blk = e / EE;
        int row = c_blkoff[blk] + __ldg(e_dst + e);
        int pos = atomicAdd(&g_cur[row], 1);
        g_sorted_src[pos] = (unsigned short)__ldg(e_src + e);
    }
}

// ---------------- F2: fused GEMM + scatter (dispatch-interleaved 2:1) ----------------
__global__ __launch_bounds__(256, 2) void gemm_scatter(
    const float* __restrict__ feats, const float* __restrict__ Ws,
    const float* __restrict__ Wn, const float* __restrict__ bias,
    float* __restrict__ out,
    const int* __restrict__ e_src, const int* __restrict__ e_dst)
{
    extern __shared__ float fsm[];
    float* AsBuf = fsm;
    float* BsBuf = fsm + 2 * AS_ELEMS;

    const int bx = blockIdx.x;
    const int p  = bx % 3;
    const int g3 = bx / 3;
    if (p < 2) {
        gemm_tile(g3 * 2 + p, feats, Ws, Wn, bias, out, AsBuf, BsBuf);
    } else {
        scatter_work(g3, e_src, e_dst);
    }
}

// ---------------- histogram (int4 vectorized) ----------------
__global__ __launch_bounds__(256) void hist_kernel(const int* __restrict__ e_dst)
{
    int i = blockIdx.x * 256 + threadIdx.x;
    if (i >= NEDGES / 4) return;
    int4 d4 = __ldg((const int4*)e_dst + i);
    int bo = c_blkoff[(i * 4) / EE];      // EE % 4 == 0 -> all 4 in same block
    atomicAdd(&g_cnt[bo + d4.x], 1);
    atomicAdd(&g_cnt[bo + d4.y], 1);
    atomicAdd(&g_cnt[bo + d4.z], 1);
    atomicAdd(&g_cnt[bo + d4.w], 1);
}

// ---------------- single-pass decoupled-lookback scan (+ blk packing) ----------------
__global__ __launch_bounds__(256) void scan_kernel()
{
    __shared__ int sm[256];
    __shared__ int s_prefix;

    const int tile  = blockIdx.x;
    const int tid   = threadIdx.x;
    const int tbase = tile * 1024;

    int4 v = *(const int4*)(g_cnt + tbase + tid * 4);
    int tsum = v.x + v.y + v.z + v.w;

    sm[tid] = tsum;
    __syncthreads();
    for (int ofs = 1; ofs < 256; ofs <<= 1) {
        int t = (tid >= ofs) ? sm[tid - ofs] : 0;
        __syncthreads();
        sm[tid] += t;
        __syncthreads();
    }
    int excl  = sm[tid] - tsum;
    int total = sm[255];

    if (tid == 0) {
        if (tile == 0) {
            atomicExch(&g_state[0], (2ULL << 32) | (unsigned)total);
            s_prefix = 0;
        } else {
            atomicExch(&g_state[tile], (1ULL << 32) | (unsigned)total);
            long long run = 0;
            int t = tile - 1;
            while (true) {
                unsigned long long st;
                do { st = atomicAdd(&g_state[t], 0ULL); } while ((st >> 32) == 0);
                run += (unsigned)st;
                if ((st >> 32) == 2) break;
                t--;
            }
            atomicExch(&g_state[tile], (2ULL << 32) | (unsigned)(run + total));
            s_prefix = (int)run;
        }
    }
    __syncthreads();

    int base = s_prefix + excl;
    int4 o;
    o.x = base;
    o.y = o.x + v.x;
    o.z = o.y + v.y;
    o.w = o.z + v.z;
    *(int4*)(g_off + tbase + tid * 4) = o;
    *(int4*)(g_cur + tbase + tid * 4) = o;

    // pack block id into g_cnt's top byte (each 1024-row tile is within one block)
    int blk = 0;
#pragma unroll
    for (int k = 1; k < 16; k++)
        if (tbase >= c_blkoff[k]) blk = k;
    int pk = blk << 24;
    int4 w = make_int4(v.x | pk, v.y | pk, v.z | pk, v.w | pk);
    *(int4*)(g_cnt + tbase + tid * 4) = w;
}

// ---------------- dummy launch: keeps gemm_scatter in ncu's capture slot ----------------
__global__ void noop_kernel() {}

// ---------------- Phase B+C fused: HALF-WARP per row (frozen body, packed blk) ----
__global__ __launch_bounds__(256) void agg_combine(
    float* __restrict__ out, const int* __restrict__ merge)
{
    const int lane = threadIdx.x & 31;
    const int sub  = lane & 15;
    const int r = blockIdx.x * 16 + ((threadIdx.x >> 5) << 1) + (lane >> 4);

    const int cntp = g_cnt[r];
    const int deg  = cntp & 0xFFFFFF;
    const int blk  = ((unsigned)cntp) >> 24;
    const int s = blk >> 2, d = blk & 3;
    const int lrow = r - c_blkoff[blk];

    const int base = g_off[r];
    const uint4* FNs = (const uint4*)(g_FN + (size_t)s * NN * OO);

    __half2 hz; *(unsigned*)&hz = 0u;
    __half2 ha0 = hz, ha1 = hz, ha2 = hz, ha3 = hz;
    __half2 hb0 = hz, hb1 = hz, hb2 = hz, hb3 = hz;

    for (int i0 = 0; i0 < deg; i0 += 16) {
        int mi = i0 + sub;
        int msrc = (mi < deg) ? (int)g_sorted_src[base + mi] : 0;
        int cnt = min(16, deg - i0);
        int fullc = cnt & ~1;
        int j = 0;
        for (; j < fullc; j += 2) {
            int s0 = __shfl_sync(0xffffffffu, msrc, j, 16);
            int s1 = __shfl_sync(0xffffffffu, msrc, j + 1, 16);
            uint4 ra = __ldg(FNs + (size_t)s0 * 16 + sub);
            uint4 rb = __ldg(FNs + (size_t)s1 * 16 + sub);
            ha0 = __hadd2(ha0, *(__half2*)&ra.x);
            ha1 = __hadd2(ha1, *(__half2*)&ra.y);
            ha2 = __hadd2(ha2, *(__half2*)&ra.z);
            ha3 = __hadd2(ha3, *(__half2*)&ra.w);
            hb0 = __hadd2(hb0, *(__half2*)&rb.x);
            hb1 = __hadd2(hb1, *(__half2*)&rb.y);
            hb2 = __hadd2(hb2, *(__half2*)&rb.z);
            hb3 = __hadd2(hb3, *(__half2*)&rb.w);
        }
        if (j < cnt) {
            int s0 = __shfl_sync(0xffffffffu, msrc, j, 16);
            uint4 ra = __ldg(FNs + (size_t)s0 * 16 + sub);
            ha0 = __hadd2(ha0, *(__half2*)&ra.x);
            ha1 = __hadd2(ha1, *(__half2*)&ra.y);
            ha2 = __hadd2(ha2, *(__half2*)&ra.z);
            ha3 = __hadd2(ha3, *(__half2*)&ra.w);
        }
    }
    ha0 = __hadd2(ha0, hb0);
    ha1 = __hadd2(ha1, hb1);
    ha2 = __hadd2(ha2, hb2);
    ha3 = __hadd2(ha3, hb3);

    float2 f0 = __half22float2(ha0);
    float2 f1 = __half22float2(ha1);
    float2 f2 = __half22float2(ha2);
    float2 f3 = __half22float2(ha3);

    const float invd = (deg > 0) ? (1.0f / (float)deg) : 0.0f;
    const int c0 = sub * 8;

    if (s == d) {
        if (deg == 0) return;
        float* op = out + ((size_t)d * NN + lrow) * OO + c0;
        asm volatile("red.global.add.v4.f32 [%0], {%1,%2,%3,%4};"
                     :: "l"(op),
                        "f"(f0.x * invd), "f"(f0.y * invd),
                        "f"(f1.x * invd), "f"(f1.y * invd) : "memory");
        asm volatile("red.global.add.v4.f32 [%0], {%1,%2,%3,%4};"
                     :: "l"(op + 4),
                        "f"(f2.x * invd), "f"(f2.y * invd),
                        "f"(f3.x * invd), "f"(f3.y * invd) : "memory");
    } else {
        uint4 smr = *(const uint4*)(g_SelfM + ((size_t)s * MM + lrow) * OO + c0);
        float2 s0 = __half22float2(*(__half2*)&smr.x);
        float2 s1 = __half22float2(*(__half2*)&smr.y);
        float2 s2 = __half22float2(*(__half2*)&smr.z);
        float2 s3 = __half22float2(*(__half2*)&smr.w);
        int tgt = __ldg(merge + (size_t)blk * MM + lrow);
        float* op = out + ((size_t)d * NN + tgt) * OO + c0;
        asm volatile("red.global.add.v4.f32 [%0], {%1,%2,%3,%4};"
                     :: "l"(op),
                        "f"(fmaf(f0.x, invd, s0.x)), "f"(fmaf(f0.y, invd, s0.y)),
                        "f"(fmaf(f1.x, invd, s1.x)), "f"(fmaf(f1.y, invd, s1.y)) : "memory");
        asm volatile("red.global.add.v4.f32 [%0], {%1,%2,%3,%4};"
                     :: "l"(op + 4),
                        "f"(fmaf(f2.x, invd, s2.x)), "f"(fmaf(f2.y, invd, s2.y)),
                        "f"(fmaf(f3.x, invd, s3.x)), "f"(fmaf(f3.y, invd, s3.y)) : "memory");
    }
}

// ---------------- launch ----------------
extern "C" void kernel_launch(void* const* d_in, const int* in_sizes, int n_in,
                              void* d_out, int out_size)
{
    const float* feats  = (const float*)d_in[0];   // [P,N,D]
    const float* Wself  = (const float*)d_in[1];   // [P,D,O]
    const float* Wneigh = (const float*)d_in[2];   // [P,D,O]
    const float* bias   = (const float*)d_in[3];   // [P,O]
    const int*   e_src  = (const int*)d_in[4];     // [P,P,E]
    const int*   e_dst  = (const int*)d_in[5];     // [P,P,E]
    const int*   merge  = (const int*)d_in[6];     // [P,P,M]
    float* out = (float*)d_out;                    // [P,N,O]

    static bool attr_set = false;
    if (!attr_set) {
        cudaFuncSetAttribute(gemm_scatter,
                             cudaFuncAttributeMaxDynamicSharedMemorySize, SMEM_BYTES);
        attr_set = true;
    }

    void* cntPtr = nullptr; cudaGetSymbolAddress(&cntPtr, g_cnt);
    void* stPtr  = nullptr; cudaGetSymbolAddress(&stPtr,  g_state);
    cudaMemsetAsync(cntPtr, 0, sizeof(int) * (size_t)TOTAL_ROWS, 0);     // launch 1
    cudaMemsetAsync(stPtr,  0, sizeof(unsigned long long) * NTILES, 0);  // launch 2

    hist_kernel<<<(NEDGES / 4 + 255) / 256, 256>>>(e_dst);               // launch 3
    scan_kernel<<<NTILES, 256>>>();                                      // launch 4
    noop_kernel<<<1, 32>>>();                                            // launch 5

    gemm_scatter<<<F2_GRID, 256, SMEM_BYTES>>>(feats, Wself, Wneigh,     // launch 6 (profiled)
                                               bias, out, e_src, e_dst);

    agg_combine<<<TOTAL_ROWS / 16, 256>>>(out, merge);                   // launch 7
}